// round 11
// baseline (speedup 1.0000x reference)
#include <cuda_runtime.h>
#include <cuda_fp16.h>
#include <cstdint>

// Problem constants (fixed by the dataset)
#define NN   100000
#define EE   1600000
#define INF  32
#define HH   128
#define CC   32
#define DD   4
#define GG   32

#define SCAN_TPB    512
#define SCAN_ELEMS  1024
#define SCAN_BLOCKS 98     // ceil(NN / 1024)

typedef unsigned long long u64;

// -------- scratch (no cudaMalloc allowed) --------
__device__ int   g_deg[NN];
__device__ int   g_cur[NN];
__device__ int   g_rowptr[NN + 2];
__device__ int   g_part[SCAN_BLOCKS];
__device__ int2  g_edge[EE];              // {src, float_bits(val)} sorted by dst

__device__ __half g_Xh[(size_t)NN * 32];  // X in fp16              [N,32]
__device__ __half g_Hh[(size_t)NN * HH];  // relu(spmm(X)@Wb), fp16 [N,128]
__device__ float g_Hm[(size_t)NN * HH];   // spmm(H)                [N,128]
__device__ float g_mz[(size_t)NN * HH];   // Hm @ Wm2 = masked_z
__device__ float g_M2[CC * CC];           // A^T (I - A^T)^{-1}
__device__ float g_Wm2[HH * HH];          // folded W_mean

// ---- packed f32x2 helpers (sm_103a FFMA2) ----
__device__ __forceinline__ u64 pk2(float lo, float hi)
{
    u64 d;
    asm("mov.b64 %0, {%1, %2};"
        : "=l"(d) : "r"(__float_as_uint(lo)), "r"(__float_as_uint(hi)));
    return d;
}
__device__ __forceinline__ void upk2(u64 v, float& lo, float& hi)
{
    unsigned a, b;
    asm("mov.b64 {%0, %1}, %2;" : "=r"(a), "=r"(b) : "l"(v));
    lo = __uint_as_float(a);
    hi = __uint_as_float(b);
}
__device__ __forceinline__ u64 fma2(u64 a, u64 b, u64 c)
{
    u64 d;
    asm("fma.rn.f32x2 %0, %1, %2, %3;" : "=l"(d) : "l"(a), "l"(b), "l"(c));
    return d;
}

// =====================================================================
// K0a: M2 = A^T @ inv(I - A^T).  One 32x32 block.
// =====================================================================
__global__ void k_prep(const float* __restrict__ A)
{
    __shared__ float B[32][33];
    __shared__ float Inv[32][33];
    int cc = threadIdx.x;
    int r  = threadIdx.y;
    B[r][cc]   = (r == cc ? 1.f : 0.f) - A[cc * 32 + r];
    Inv[r][cc] = (r == cc ? 1.f : 0.f);
    __syncthreads();

    for (int k = 0; k < 32; k++) {
        float piv = B[k][k];
        __syncthreads();
        if (r == k) {
            float inv = 1.f / piv;
            B[k][cc]   *= inv;
            Inv[k][cc] *= inv;
        }
        __syncthreads();
        float f  = B[r][k];
        float bk = B[k][cc];
        float ik = Inv[k][cc];
        __syncthreads();
        if (r != k) {
            B[r][cc]   -= f * bk;
            Inv[r][cc] -= f * ik;
        }
        __syncthreads();
    }
    float acc = 0.f;
    #pragma unroll
    for (int j = 0; j < 32; j++)
        acc += A[j * 32 + r] * Inv[j][cc];
    g_M2[r * 32 + cc] = acc;
}

// =====================================================================
// K0b: Wm2[h, c*4+d] = sum_k M2[c,k] * Wm[h, k*4+d]
// =====================================================================
__global__ void k_fold(const float* __restrict__ Wm)
{
    int idx = blockIdx.x * blockDim.x + threadIdx.x;
    int h  = idx >> 7;
    int cd = idx & 127;
    int c  = cd >> 2;
    int d  = cd & 3;
    float acc = 0.f;
    #pragma unroll
    for (int k = 0; k < 32; k++)
        acc += g_M2[c * 32 + k] * Wm[h * 128 + k * 4 + d];
    g_Wm2[h * 128 + cd] = acc;
}

// =====================================================================
// Convert X to fp16 (vectorized: float4 -> 4 halves)
// =====================================================================
__global__ void k_xcvt(const float* __restrict__ X)
{
    int i = blockIdx.x * blockDim.x + threadIdx.x;
    int stride = gridDim.x * blockDim.x;
    int n4 = NN * 32 / 4;
    for (int j = i; j < n4; j += stride) {
        float4 v = reinterpret_cast<const float4*>(X)[j];
        __half2 a = __floats2half2_rn(v.x, v.y);
        __half2 b = __floats2half2_rn(v.z, v.w);
        uint2 pk;
        pk.x = *reinterpret_cast<unsigned*>(&a);
        pk.y = *reinterpret_cast<unsigned*>(&b);
        reinterpret_cast<uint2*>(g_Xh)[j] = pk;
    }
}

// =====================================================================
// Counting sort of edges by dst
// =====================================================================
__global__ void k_zero_deg()
{
    int i = blockIdx.x * blockDim.x + threadIdx.x;
    if (i < NN) g_deg[i] = 0;
}

__global__ void k_hist(const int* __restrict__ dst)
{
    int i = blockIdx.x * blockDim.x + threadIdx.x;
    int stride = gridDim.x * blockDim.x;
    for (int e = i; e < EE; e += stride)
        atomicAdd(&g_deg[__ldg(dst + e)], 1);
}

__global__ void k_scan1()
{
    __shared__ int wsum[16];
    int tid  = threadIdx.x;
    int base = blockIdx.x * SCAN_ELEMS;
    int i0   = base + 2 * tid;
    int a = (i0     < NN) ? g_deg[i0]     : 0;
    int b = (i0 + 1 < NN) ? g_deg[i0 + 1] : 0;
    int s = a + b;
    int lane = tid & 31, w = tid >> 5;
    int incl = s;
    #pragma unroll
    for (int d = 1; d < 32; d <<= 1) {
        int t = __shfl_up_sync(0xffffffff, incl, d);
        if (lane >= d) incl += t;
    }
    if (lane == 31) wsum[w] = incl;
    __syncthreads();
    if (tid < 16) {
        int v = wsum[tid];
        int iv = v;
        #pragma unroll
        for (int d = 1; d < 16; d <<= 1) {
            int t = __shfl_up_sync(0xffff, iv, d);
            if (tid >= d) iv += t;
        }
        wsum[tid] = iv - v;
    }
    __syncthreads();
    int excl = wsum[w] + incl - s;
    if (i0 <= NN)     g_rowptr[i0]     = excl;
    if (i0 + 1 <= NN) g_rowptr[i0 + 1] = excl + a;
    if (tid == SCAN_TPB - 1) g_part[blockIdx.x] = excl + s;
}

__global__ void k_scan2()
{
    if (threadIdx.x == 0) {
        int run = 0;
        for (int i = 0; i < SCAN_BLOCKS; i++) {
            int v = g_part[i];
            g_part[i] = run;
            run += v;
        }
    }
}

__global__ void k_scan3()
{
    int i = blockIdx.x * blockDim.x + threadIdx.x;
    if (i <= NN) {
        int r = g_rowptr[i] + g_part[i >> 10];
        g_rowptr[i] = r;
        if (i < NN) g_cur[i] = r;
    }
}

__global__ void k_scatter(const int* __restrict__ src,
                          const int* __restrict__ dst,
                          const float* __restrict__ val)
{
    int i = blockIdx.x * blockDim.x + threadIdx.x;
    int stride = gridDim.x * blockDim.x;
    for (int e = i; e < EE; e += stride) {
        int d = __ldg(dst + e);
        int pos = atomicAdd(&g_cur[d], 1);
        g_edge[pos] = make_int2(__ldg(src + e), __float_as_int(__ldg(val + e)));
    }
}

// =====================================================================
// k_enc: fused  T = spmm(Xh) ;  H = relu(T @ W_base), stored fp16
// warp per node (grid-stride). X gathered as fp16 (64B rows).
// =====================================================================
__global__ void __launch_bounds__(256) k_enc(const float* __restrict__ Wb)
{
    __shared__ float Ws[32 * 128];   // W_base, row-major [k][j]
    __shared__ float Ts[8][34];      // per-warp T broadcast buffer
    int tid = threadIdx.x;
    for (int i = tid; i < 32 * 128; i += 256) Ws[i] = Wb[i];
    __syncthreads();

    const int lane = tid & 31;
    const int warp = tid >> 5;
    unsigned gw = blockIdx.x * 8 + warp;
    unsigned nw = gridDim.x * 8;
    const float4* Ws4 = reinterpret_cast<const float4*>(Ws);

    for (unsigned n = gw; n < NN; n += nw) {
        int s0 = g_rowptr[n], s1 = g_rowptr[n + 1];
        float acc = 0.f;
        int e = s0;
        for (; e + 4 <= s1; e += 4) {
            int2 p0 = g_edge[e],     p1 = g_edge[e + 1];
            int2 p2 = g_edge[e + 2], p3 = g_edge[e + 3];
            float x0 = __half2float(g_Xh[(size_t)p0.x * 32 + lane]);
            float x1 = __half2float(g_Xh[(size_t)p1.x * 32 + lane]);
            float x2 = __half2float(g_Xh[(size_t)p2.x * 32 + lane]);
            float x3 = __half2float(g_Xh[(size_t)p3.x * 32 + lane]);
            acc = fmaf(__int_as_float(p0.y), x0, acc);
            acc = fmaf(__int_as_float(p1.y), x1, acc);
            acc = fmaf(__int_as_float(p2.y), x2, acc);
            acc = fmaf(__int_as_float(p3.y), x3, acc);
        }
        for (; e < s1; e++) {
            int2 p = g_edge[e];
            acc = fmaf(__int_as_float(p.y),
                       __half2float(g_Xh[(size_t)p.x * 32 + lane]), acc);
        }
        Ts[warp][lane] = acc;
        __syncwarp();

        float4 h = make_float4(0.f, 0.f, 0.f, 0.f);
        #pragma unroll
        for (int k = 0; k < 32; k++) {
            float tk = Ts[warp][k];
            float4 wv = Ws4[k * 32 + lane];
            h.x = fmaf(tk, wv.x, h.x); h.y = fmaf(tk, wv.y, h.y);
            h.z = fmaf(tk, wv.z, h.z); h.w = fmaf(tk, wv.w, h.w);
        }
        h.x = h.x > 0.f ? h.x : 0.f; h.y = h.y > 0.f ? h.y : 0.f;
        h.z = h.z > 0.f ? h.z : 0.f; h.w = h.w > 0.f ? h.w : 0.f;
        __half2 a = __floats2half2_rn(h.x, h.y);
        __half2 b = __floats2half2_rn(h.z, h.w);
        uint2 pk;
        pk.x = *reinterpret_cast<unsigned*>(&a);
        pk.y = *reinterpret_cast<unsigned*>(&b);
        reinterpret_cast<uint2*>(g_Hh)[(size_t)n * 32 + lane] = pk;
        __syncwarp();
    }
}

// =====================================================================
// spmm wide: Hm[n,:128] = sum_{e in row n} val[e] * H[src[e], :128]
// warp per node, lane handles 4 columns (one 8B fp16x4 load per edge).
// =====================================================================
__global__ void __launch_bounds__(256) k_spmm_wide()
{
    int lane = threadIdx.x & 31;
    int n = (blockIdx.x * blockDim.x + threadIdx.x) >> 5;
    if (n >= NN) return;
    int s0 = g_rowptr[n], s1 = g_rowptr[n + 1];
    const uint2* Hp = reinterpret_cast<const uint2*>(g_Hh);
    float4 acc = make_float4(0.f, 0.f, 0.f, 0.f);
    int e = s0;
    for (; e + 4 <= s1; e += 4) {
        int2 p0 = g_edge[e],     p1 = g_edge[e + 1];
        int2 p2 = g_edge[e + 2], p3 = g_edge[e + 3];
        float v0 = __int_as_float(p0.y), v1 = __int_as_float(p1.y);
        float v2 = __int_as_float(p2.y), v3 = __int_as_float(p3.y);
        uint2 r0 = __ldg(Hp + (size_t)p0.x * 32 + lane);
        uint2 r1 = __ldg(Hp + (size_t)p1.x * 32 + lane);
        uint2 r2 = __ldg(Hp + (size_t)p2.x * 32 + lane);
        uint2 r3 = __ldg(Hp + (size_t)p3.x * 32 + lane);
        float2 a0 = __half22float2(*reinterpret_cast<__half2*>(&r0.x));
        float2 b0 = __half22float2(*reinterpret_cast<__half2*>(&r0.y));
        float2 a1 = __half22float2(*reinterpret_cast<__half2*>(&r1.x));
        float2 b1 = __half22float2(*reinterpret_cast<__half2*>(&r1.y));
        float2 a2 = __half22float2(*reinterpret_cast<__half2*>(&r2.x));
        float2 b2 = __half22float2(*reinterpret_cast<__half2*>(&r2.y));
        float2 a3 = __half22float2(*reinterpret_cast<__half2*>(&r3.x));
        float2 b3 = __half22float2(*reinterpret_cast<__half2*>(&r3.y));
        acc.x = fmaf(v0, a0.x, acc.x); acc.y = fmaf(v0, a0.y, acc.y);
        acc.z = fmaf(v0, b0.x, acc.z); acc.w = fmaf(v0, b0.y, acc.w);
        acc.x = fmaf(v1, a1.x, acc.x); acc.y = fmaf(v1, a1.y, acc.y);
        acc.z = fmaf(v1, b1.x, acc.z); acc.w = fmaf(v1, b1.y, acc.w);
        acc.x = fmaf(v2, a2.x, acc.x); acc.y = fmaf(v2, a2.y, acc.y);
        acc.z = fmaf(v2, b2.x, acc.z); acc.w = fmaf(v2, b2.y, acc.w);
        acc.x = fmaf(v3, a3.x, acc.x); acc.y = fmaf(v3, a3.y, acc.y);
        acc.z = fmaf(v3, b3.x, acc.z); acc.w = fmaf(v3, b3.y, acc.w);
    }
    for (; e < s1; e++) {
        int2 p = g_edge[e];
        float v = __int_as_float(p.y);
        uint2 r0 = __ldg(Hp + (size_t)p.x * 32 + lane);
        float2 a0 = __half22float2(*reinterpret_cast<__half2*>(&r0.x));
        float2 b0 = __half22float2(*reinterpret_cast<__half2*>(&r0.y));
        acc.x = fmaf(v, a0.x, acc.x); acc.y = fmaf(v, a0.y, acc.y);
        acc.z = fmaf(v, b0.x, acc.z); acc.w = fmaf(v, b0.y, acc.w);
    }
    reinterpret_cast<float4*>(g_Hm)[(size_t)n * 32 + lane] = acc;
}

// =====================================================================
// K3: mz = Hm @ Wm2   [N,128]@[128,128]  (proven R6 tiling)
// =====================================================================
#define HS_STRIDE 132
#define MM_SMEM   ((64 * HS_STRIDE + 32 * 128) * 4)   // 50176 bytes

__global__ void __launch_bounds__(256) k_mm()
{
    extern __shared__ float dsm[];
    float* Hs = dsm;                     // [64][132]
    float* Wt = dsm + 64 * HS_STRIDE;    // [32][128]
    int tid  = threadIdx.x;
    int base = blockIdx.x * 64;

    for (int i = tid; i < 64 * 128; i += 256) {
        int r = i >> 7, k = i & 127;
        int row = base + r;
        Hs[r * HS_STRIDE + k] = (row < NN) ? g_Hm[(size_t)row * 128 + k] : 0.f;
    }

    const int tx = tid & 15;
    const int ty = tid >> 4;
    const int j0 = tx * 4;
    const int r0 = ty * 4;
    float acc[4][8];
    #pragma unroll
    for (int r = 0; r < 4; r++)
        #pragma unroll
        for (int c = 0; c < 8; c++) acc[r][c] = 0.f;

    for (int k0 = 0; k0 < 128; k0 += 32) {
        __syncthreads();
        for (int i = tid; i < 32 * 128; i += 256)
            Wt[i] = g_Wm2[(size_t)(k0 + (i >> 7)) * 128 + (i & 127)];
        __syncthreads();
        #pragma unroll
        for (int kk = 0; kk < 32; kk++) {
            float4 wa = *reinterpret_cast<const float4*>(&Wt[kk * 128 + j0]);
            float4 wb = *reinterpret_cast<const float4*>(&Wt[kk * 128 + 64 + j0]);
            #pragma unroll
            for (int r = 0; r < 4; r++) {
                float h = Hs[(r0 + r) * HS_STRIDE + k0 + kk];
                acc[r][0] = fmaf(h, wa.x, acc[r][0]);
                acc[r][1] = fmaf(h, wa.y, acc[r][1]);
                acc[r][2] = fmaf(h, wa.z, acc[r][2]);
                acc[r][3] = fmaf(h, wa.w, acc[r][3]);
                acc[r][4] = fmaf(h, wb.x, acc[r][4]);
                acc[r][5] = fmaf(h, wb.y, acc[r][5]);
                acc[r][6] = fmaf(h, wb.z, acc[r][6]);
                acc[r][7] = fmaf(h, wb.w, acc[r][7]);
            }
        }
    }
    #pragma unroll
    for (int r = 0; r < 4; r++) {
        int row = base + r0 + r;
        if (row < NN) {
            float4 oa = make_float4(acc[r][0], acc[r][1], acc[r][2], acc[r][3]);
            float4 ob = make_float4(acc[r][4], acc[r][5], acc[r][6], acc[r][7]);
            *reinterpret_cast<float4*>(&g_mz[(size_t)row * 128 + j0])      = oa;
            *reinterpret_cast<float4*>(&g_mz[(size_t)row * 128 + 64 + j0]) = ob;
        }
    }
}

// =====================================================================
// K5: fused epilogue. Warp per node-PAIR, packed f32x2 (A=lo, B=hi).
// =====================================================================
#define OFF_W1   0
#define OFF_W2   4224
#define OFF_CST  8448
#define OFF_AT   12672
#define OFF_WREC 16896
#define OFF_BZ2  21120
#define OFF_BL2  21248
#define OFF_BREC 21280
// u64 z-buffer: starts at float offset 21312 (byte 85248, 16B aligned)
#define ZBUF_U64_BASE   (21312 / 2)           // u64 index into smem
#define ZBUF_U64_STRIDE 130                   // per warp (128 + 2 pad)
#define OFF_LAB  (21312 + 8 * ZBUF_U64_STRIDE * 2)   // = 23392
#define SMEM_FLOATS (OFF_LAB + 8 * 64)        // 23904 floats = 95616 bytes

__global__ void __launch_bounds__(256) k_epi(
    const float* __restrict__ label, const float* __restrict__ noise,
    const float* __restrict__ A,
    const float* __restrict__ Wz1, const float* __restrict__ bz1,
    const float* __restrict__ Wz2, const float* __restrict__ bz2,
    const float* __restrict__ Wl1, const float* __restrict__ bl1,
    const float* __restrict__ Wl2, const float* __restrict__ bl2,
    const float* __restrict__ Wrec, const float* __restrict__ brec,
    float* __restrict__ out_rec, float* __restrict__ out_pred)
{
    extern __shared__ float sm[];
    int tid = threadIdx.x;

    for (int i = tid; i < 4096; i += 256) {
        int c = i >> 7, r = i & 127, g = r >> 2, d = r & 3;
        sm[OFF_W1 + c * 132 + g * 4 + d] = Wz1[c * 128 + d * 32 + g];
        sm[OFF_W2 + c * 132 + g * 4 + d] = Wz2[c * 128 + g * 4 + d];
        int k = i >> 5, j = i & 31;
        sm[OFF_WREC + j * 132 + k] = Wrec[k * 32 + j];
    }
    for (int i = tid; i < 1024; i += 256) {
        int k = i >> 5, c = i & 31;
        sm[OFF_AT + c * 132 + k] = A[k * 32 + c];
        int cc = i >> 5, g = i & 31;
        float* p = sm + OFF_CST + cc * 132 + g * 4;
        p[0] = bz1[cc * 32 + g];
        p[1] = Wl1[cc * 32 + g];
        p[2] = bl1[cc * 32 + g];
        p[3] = Wl2[cc * 32 + g];
    }
    for (int i = tid; i < 128; i += 256) sm[OFF_BZ2 + i] = bz2[i];
    if (tid < 32) { sm[OFF_BL2 + tid] = bl2[tid]; sm[OFF_BREC + tid] = brec[tid]; }
    __syncthreads();

    const int warp = tid >> 5;
    const int lane = tid & 31;
    unsigned gw = blockIdx.x * 8 + warp;
    unsigned nwrp = gridDim.x * 8;

    u64* zwp = reinterpret_cast<u64*>(sm) + ZBUF_U64_BASE + warp * ZBUF_U64_STRIDE;
    float* lbA = sm + OFF_LAB + warp * 64;
    float* lbB = lbA + 32;
    const float* w1p = sm + OFF_W1   + lane * 132;
    const float* w2p = sm + OFF_W2   + lane * 132;
    const float* csp = sm + OFF_CST  + lane * 132;
    const float* atp = sm + OFF_AT   + lane * 132;
    const float* wrp = sm + OFF_WREC + lane * 132;
    const float  SQL = 0.0316227766016838f;   // sqrt(1e-3)

    // NN is even: pair (n, n+1) always valid when n < NN
    for (unsigned n = gw * 2; n < NN; n += nwrp * 2) {
        unsigned nA = n, nB = n + 1;
        float4 mzA = *reinterpret_cast<const float4*>(g_mz + (size_t)nA * 128 + lane * 4);
        float4 mzB = *reinterpret_cast<const float4*>(g_mz + (size_t)nB * 128 + lane * 4);
        float4 nzA = __ldg(reinterpret_cast<const float4*>(noise + (size_t)nA * 128) + lane);
        float4 nzB = __ldg(reinterpret_cast<const float4*>(noise + (size_t)nB * 128) + lane);
        lbA[lane] = __ldg(label + (size_t)nA * 32 + lane);
        lbB[lane] = __ldg(label + (size_t)nB * 32 + lane);
        __syncwarp();

        float mlA = 0.f, mlB = 0.f;
        #pragma unroll
        for (int k = 0; k < 32; k += 4) {
            float4 a4 = *reinterpret_cast<const float4*>(atp + k);
            float4 lA = *reinterpret_cast<const float4*>(lbA + k);
            float4 lB = *reinterpret_cast<const float4*>(lbB + k);
            mlA = fmaf(lA.x, a4.x, mlA); mlA = fmaf(lA.y, a4.y, mlA);
            mlA = fmaf(lA.z, a4.z, mlA); mlA = fmaf(lA.w, a4.w, mlA);
            mlB = fmaf(lB.x, a4.x, mlB); mlB = fmaf(lB.y, a4.y, mlB);
            mlB = fmaf(lB.z, a4.z, mlB); mlB = fmaf(lB.w, a4.w, mlB);
        }

        // pack A (lo) / B (hi)
        u64 mzx = pk2(mzA.x, mzB.x);
        u64 mzy = pk2(mzA.y, mzB.y);
        u64 mzz = pk2(mzA.z, mzB.z);
        u64 mzw = pk2(mzA.w, mzB.w);
        u64 mlp = pk2(mlA, mlB);

        float4 bz = *reinterpret_cast<const float4*>(sm + OFF_BZ2 + lane * 4);
        u64 z2x = pk2(bz.x, bz.x);
        u64 z2y = pk2(bz.y, bz.y);
        u64 z2z = pk2(bz.z, bz.z);
        u64 z2w = pk2(bz.w, bz.w);
        float pl = sm[OFF_BL2 + lane];
        u64 pred = pk2(pl, pl);

        #pragma unroll 4
        for (int g = 0; g < 32; g++) {
            float4 w1 = *reinterpret_cast<const float4*>(w1p + g * 4);
            float4 cs = *reinterpret_cast<const float4*>(csp + g * 4);
            float4 w2 = *reinterpret_cast<const float4*>(w2p + g * 4);

            u64 t = pk2(cs.x, cs.x);
            t = fma2(mzx, pk2(w1.x, w1.x), t);
            t = fma2(mzy, pk2(w1.y, w1.y), t);
            t = fma2(mzz, pk2(w1.z, w1.z), t);
            t = fma2(mzw, pk2(w1.w, w1.w), t);
            float tA, tB;
            upk2(t, tA, tB);
            float hzA = tA > 0.f ? tA : (__expf(tA) - 1.f);
            float hzB = tB > 0.f ? tB : (__expf(tB) - 1.f);
            u64 hz = pk2(hzA, hzB);
            z2x = fma2(hz, pk2(w2.x, w2.x), z2x);
            z2y = fma2(hz, pk2(w2.y, w2.y), z2y);
            z2z = fma2(hz, pk2(w2.z, w2.z), z2z);
            z2w = fma2(hz, pk2(w2.w, w2.w), z2w);

            u64 tl = fma2(mlp, pk2(cs.y, cs.y), pk2(cs.z, cs.z));
            float tlA, tlB;
            upk2(tl, tlA, tlB);
            float hlA = tlA > 0.f ? tlA : (__expf(tlA) - 1.f);
            float hlB = tlB > 0.f ? tlB : (__expf(tlB) - 1.f);
            pred = fma2(pk2(hlA, hlB), pk2(cs.w, cs.w), pred);
        }

        // z = masked_z + sqrt(lambdav)*noise  (packed), store packed to smem
        u64 s2 = pk2(SQL, SQL);
        u64 zx = fma2(s2, pk2(nzA.x, nzB.x), z2x);
        u64 zy = fma2(s2, pk2(nzA.y, nzB.y), z2y);
        u64 zz = fma2(s2, pk2(nzA.z, nzB.z), z2z);
        u64 zw = fma2(s2, pk2(nzA.w, nzB.w), z2w);
        *reinterpret_cast<ulonglong2*>(zwp + lane * 4)     = make_ulonglong2(zx, zy);
        *reinterpret_cast<ulonglong2*>(zwp + lane * 4 + 2) = make_ulonglong2(zz, zw);
        __syncwarp();

        // rec[j] = brec[j] + sum_k z[k] * Wrec[k][j]  (packed A/B)
        float bc = sm[OFF_BREC + lane];
        u64 acc = pk2(bc, bc);
        #pragma unroll
        for (int k = 0; k < 128; k += 4) {
            ulonglong2 q0 = *reinterpret_cast<const ulonglong2*>(zwp + k);
            ulonglong2 q1 = *reinterpret_cast<const ulonglong2*>(zwp + k + 2);
            float4 wr = *reinterpret_cast<const float4*>(wrp + k);
            acc = fma2(q0.x, pk2(wr.x, wr.x), acc);
            acc = fma2(q0.y, pk2(wr.y, wr.y), acc);
            acc = fma2(q1.x, pk2(wr.z, wr.z), acc);
            acc = fma2(q1.y, pk2(wr.w, wr.w), acc);
        }
        float accA, accB, predA, predB;
        upk2(acc, accA, accB);
        upk2(pred, predA, predB);
        out_rec[(size_t)nA * 32 + lane]  = accA;
        out_rec[(size_t)nB * 32 + lane]  = accB;
        out_pred[(size_t)nA * 32 + lane] = predA;
        out_pred[(size_t)nB * 32 + lane] = predB;
        __syncwarp();
    }
}

// =====================================================================
// launch
// =====================================================================
extern "C" void kernel_launch(void* const* d_in, const int* in_sizes, int n_in,
                              void* d_out, int out_size)
{
    const float* X      = (const float*)d_in[0];
    const float* label  = (const float*)d_in[1];
    const float* eval_  = (const float*)d_in[2];
    const float* noise  = (const float*)d_in[3];
    const float* Wb     = (const float*)d_in[4];
    const float* Wm     = (const float*)d_in[5];
    // d_in[6] = W_logstd -> result discarded in reference, skipped entirely
    const float* A      = (const float*)d_in[7];
    const float* Wz1    = (const float*)d_in[8];
    const float* bz1    = (const float*)d_in[9];
    const float* Wz2    = (const float*)d_in[10];
    const float* bz2    = (const float*)d_in[11];
    const float* Wl1    = (const float*)d_in[12];
    const float* bl1    = (const float*)d_in[13];
    const float* Wl2    = (const float*)d_in[14];
    const float* bl2    = (const float*)d_in[15];
    const float* Wrec   = (const float*)d_in[16];
    const float* brec   = (const float*)d_in[17];
    const int*   esrc   = (const int*)d_in[18];
    const int*   edst   = (const int*)d_in[19];

    float* out_rec  = (float*)d_out;
    float* out_pred = out_rec + (size_t)NN * 32;

    cudaFuncSetAttribute(k_epi, cudaFuncAttributeMaxDynamicSharedMemorySize,
                         SMEM_FLOATS * (int)sizeof(float));
    cudaFuncSetAttribute(k_mm, cudaFuncAttributeMaxDynamicSharedMemorySize,
                         MM_SMEM);

    // tiny weight prep + X fp16 conversion
    k_prep<<<1, dim3(32, 32)>>>(A);
    k_fold<<<64, 256>>>(Wm);
    k_xcvt<<<800, 256>>>(X);

    // counting sort of edges by dst -> CSR (paired {src, val})
    k_zero_deg<<<(NN + 255) / 256, 256>>>();
    k_hist<<<2048, 256>>>(edst);
    k_scan1<<<SCAN_BLOCKS, SCAN_TPB>>>();
    k_scan2<<<1, 32>>>();
    k_scan3<<<(NN + 256) / 256, 256>>>();
    k_scatter<<<2048, 256>>>(esrc, edst, eval_);

    // main pipeline
    k_enc<<<1536, 256>>>(Wb);                           // H = relu(spmm(Xh) @ Wb), fp16
    k_spmm_wide<<<(NN * 32 + 255) / 256, 256>>>();      // Hm = spmm(H)  (fp32 accum)
    k_mm<<<(NN + 63) / 64, 256, MM_SMEM>>>();           // mz = Hm @ Wm2
    k_epi<<<296, 256, SMEM_FLOATS * sizeof(float)>>>(
        label, noise, A, Wz1, bz1, Wz2, bz2, Wl1, bl1, Wl2, bl2,
        Wrec, brec, out_rec, out_pred);
}

// round 14
// speedup vs baseline: 1.0240x; 1.0240x over previous
#include <cuda_runtime.h>
#include <cuda_fp16.h>
#include <cstdint>

// Problem constants (fixed by the dataset)
#define NN   100000
#define EE   1600000
#define INF  32
#define HH   128
#define CC   32
#define DD   4
#define GG   32

#define SCAN_TPB    512
#define SCAN_ELEMS  1024
#define SCAN_BLOCKS 98     // ceil(NN / 1024)

// -------- scratch (no cudaMalloc allowed) --------
__device__ int   g_deg[NN];
__device__ int   g_cur[NN];
__device__ int   g_rowptr[NN + 2];
__device__ int   g_part[SCAN_BLOCKS];
__device__ int2  g_edge[EE];              // {src, float_bits(val)} sorted by dst

__device__ __half g_Xh[(size_t)NN * 32];  // X in fp16              [N,32]
__device__ __half g_Hh[(size_t)NN * HH];  // relu(spmm(X)@Wb), fp16 [N,128]
__device__ float g_Hm[(size_t)NN * HH];   // spmm(H)                [N,128]
__device__ float g_mz[(size_t)NN * HH];   // Hm @ Wm2 = masked_z
__device__ float g_M2[CC * CC];           // A^T (I - A^T)^{-1}
__device__ float g_Wm2[HH * HH];          // folded W_mean

// =====================================================================
// K0a: M2 = A^T @ inv(I - A^T).  One 32x32 block.
// =====================================================================
__global__ void k_prep(const float* __restrict__ A)
{
    __shared__ float B[32][33];
    __shared__ float Inv[32][33];
    int cc = threadIdx.x;
    int r  = threadIdx.y;
    B[r][cc]   = (r == cc ? 1.f : 0.f) - A[cc * 32 + r];
    Inv[r][cc] = (r == cc ? 1.f : 0.f);
    __syncthreads();

    for (int k = 0; k < 32; k++) {
        float piv = B[k][k];
        __syncthreads();
        if (r == k) {
            float inv = 1.f / piv;
            B[k][cc]   *= inv;
            Inv[k][cc] *= inv;
        }
        __syncthreads();
        float f  = B[r][k];
        float bk = B[k][cc];
        float ik = Inv[k][cc];
        __syncthreads();
        if (r != k) {
            B[r][cc]   -= f * bk;
            Inv[r][cc] -= f * ik;
        }
        __syncthreads();
    }
    float acc = 0.f;
    #pragma unroll
    for (int j = 0; j < 32; j++)
        acc += A[j * 32 + r] * Inv[j][cc];
    g_M2[r * 32 + cc] = acc;
}

// =====================================================================
// K0b: Wm2[h, c*4+d] = sum_k M2[c,k] * Wm[h, k*4+d]
// =====================================================================
__global__ void k_fold(const float* __restrict__ Wm)
{
    int idx = blockIdx.x * blockDim.x + threadIdx.x;
    int h  = idx >> 7;
    int cd = idx & 127;
    int c  = cd >> 2;
    int d  = cd & 3;
    float acc = 0.f;
    #pragma unroll
    for (int k = 0; k < 32; k++)
        acc += g_M2[c * 32 + k] * Wm[h * 128 + k * 4 + d];
    g_Wm2[h * 128 + cd] = acc;
}

// =====================================================================
// Convert X to fp16 (vectorized: float4 -> 4 halves)
// =====================================================================
__global__ void k_xcvt(const float* __restrict__ X)
{
    int i = blockIdx.x * blockDim.x + threadIdx.x;
    int stride = gridDim.x * blockDim.x;
    int n4 = NN * 32 / 4;
    for (int j = i; j < n4; j += stride) {
        float4 v = reinterpret_cast<const float4*>(X)[j];
        __half2 a = __floats2half2_rn(v.x, v.y);
        __half2 b = __floats2half2_rn(v.z, v.w);
        uint2 pk;
        pk.x = *reinterpret_cast<unsigned*>(&a);
        pk.y = *reinterpret_cast<unsigned*>(&b);
        reinterpret_cast<uint2*>(g_Xh)[j] = pk;
    }
}

// =====================================================================
// Counting sort of edges by dst
// =====================================================================
__global__ void k_zero_deg()
{
    int i = blockIdx.x * blockDim.x + threadIdx.x;
    if (i < NN) g_deg[i] = 0;
}

__global__ void k_hist(const int* __restrict__ dst)
{
    int i = blockIdx.x * blockDim.x + threadIdx.x;
    int stride = gridDim.x * blockDim.x;
    for (int e = i; e < EE; e += stride)
        atomicAdd(&g_deg[__ldg(dst + e)], 1);
}

__global__ void k_scan1()
{
    __shared__ int wsum[16];
    int tid  = threadIdx.x;
    int base = blockIdx.x * SCAN_ELEMS;
    int i0   = base + 2 * tid;
    int a = (i0     < NN) ? g_deg[i0]     : 0;
    int b = (i0 + 1 < NN) ? g_deg[i0 + 1] : 0;
    int s = a + b;
    int lane = tid & 31, w = tid >> 5;
    int incl = s;
    #pragma unroll
    for (int d = 1; d < 32; d <<= 1) {
        int t = __shfl_up_sync(0xffffffff, incl, d);
        if (lane >= d) incl += t;
    }
    if (lane == 31) wsum[w] = incl;
    __syncthreads();
    if (tid < 16) {
        int v = wsum[tid];
        int iv = v;
        #pragma unroll
        for (int d = 1; d < 16; d <<= 1) {
            int t = __shfl_up_sync(0xffff, iv, d);
            if (tid >= d) iv += t;
        }
        wsum[tid] = iv - v;
    }
    __syncthreads();
    int excl = wsum[w] + incl - s;
    if (i0 <= NN)     g_rowptr[i0]     = excl;
    if (i0 + 1 <= NN) g_rowptr[i0 + 1] = excl + a;
    if (tid == SCAN_TPB - 1) g_part[blockIdx.x] = excl + s;
}

__global__ void k_scan2()
{
    if (threadIdx.x == 0) {
        int run = 0;
        for (int i = 0; i < SCAN_BLOCKS; i++) {
            int v = g_part[i];
            g_part[i] = run;
            run += v;
        }
    }
}

__global__ void k_scan3()
{
    int i = blockIdx.x * blockDim.x + threadIdx.x;
    if (i <= NN) {
        int r = g_rowptr[i] + g_part[i >> 10];
        g_rowptr[i] = r;
        if (i < NN) g_cur[i] = r;
    }
}

__global__ void k_scatter(const int* __restrict__ src,
                          const int* __restrict__ dst,
                          const float* __restrict__ val)
{
    int i = blockIdx.x * blockDim.x + threadIdx.x;
    int stride = gridDim.x * blockDim.x;
    for (int e = i; e < EE; e += stride) {
        int d = __ldg(dst + e);
        int pos = atomicAdd(&g_cur[d], 1);
        g_edge[pos] = make_int2(__ldg(src + e), __float_as_int(__ldg(val + e)));
    }
}

// =====================================================================
// k_enc: fused  T = spmm(Xh) ;  H = relu(T @ W_base), stored fp16
// warp per node (grid-stride). X gathered as fp16 (64B rows).
// =====================================================================
__global__ void __launch_bounds__(256) k_enc(const float* __restrict__ Wb)
{
    __shared__ float Ws[32 * 128];   // W_base, row-major [k][j]
    __shared__ float Ts[8][34];      // per-warp T broadcast buffer
    int tid = threadIdx.x;
    for (int i = tid; i < 32 * 128; i += 256) Ws[i] = Wb[i];
    __syncthreads();

    const int lane = tid & 31;
    const int warp = tid >> 5;
    unsigned gw = blockIdx.x * 8 + warp;
    unsigned nw = gridDim.x * 8;
    const float4* Ws4 = reinterpret_cast<const float4*>(Ws);

    for (unsigned n = gw; n < NN; n += nw) {
        int s0 = g_rowptr[n], s1 = g_rowptr[n + 1];
        float acc = 0.f;
        int e = s0;
        for (; e + 4 <= s1; e += 4) {
            int2 p0 = g_edge[e],     p1 = g_edge[e + 1];
            int2 p2 = g_edge[e + 2], p3 = g_edge[e + 3];
            float x0 = __half2float(g_Xh[(size_t)p0.x * 32 + lane]);
            float x1 = __half2float(g_Xh[(size_t)p1.x * 32 + lane]);
            float x2 = __half2float(g_Xh[(size_t)p2.x * 32 + lane]);
            float x3 = __half2float(g_Xh[(size_t)p3.x * 32 + lane]);
            acc = fmaf(__int_as_float(p0.y), x0, acc);
            acc = fmaf(__int_as_float(p1.y), x1, acc);
            acc = fmaf(__int_as_float(p2.y), x2, acc);
            acc = fmaf(__int_as_float(p3.y), x3, acc);
        }
        for (; e < s1; e++) {
            int2 p = g_edge[e];
            acc = fmaf(__int_as_float(p.y),
                       __half2float(g_Xh[(size_t)p.x * 32 + lane]), acc);
        }
        Ts[warp][lane] = acc;
        __syncwarp();

        float4 h = make_float4(0.f, 0.f, 0.f, 0.f);
        #pragma unroll
        for (int k = 0; k < 32; k++) {
            float tk = Ts[warp][k];
            float4 wv = Ws4[k * 32 + lane];
            h.x = fmaf(tk, wv.x, h.x); h.y = fmaf(tk, wv.y, h.y);
            h.z = fmaf(tk, wv.z, h.z); h.w = fmaf(tk, wv.w, h.w);
        }
        h.x = h.x > 0.f ? h.x : 0.f; h.y = h.y > 0.f ? h.y : 0.f;
        h.z = h.z > 0.f ? h.z : 0.f; h.w = h.w > 0.f ? h.w : 0.f;
        __half2 a = __floats2half2_rn(h.x, h.y);
        __half2 b = __floats2half2_rn(h.z, h.w);
        uint2 pk;
        pk.x = *reinterpret_cast<unsigned*>(&a);
        pk.y = *reinterpret_cast<unsigned*>(&b);
        reinterpret_cast<uint2*>(g_Hh)[(size_t)n * 32 + lane] = pk;
        __syncwarp();
    }
}

// =====================================================================
// spmm wide: Hm[n,:128] = sum_{e in row n} val[e] * H[src[e], :128]
// warp per node, lane handles 4 columns (one 8B fp16x4 load per edge).
// Accumulation in fp32; only the stored H operand is fp16.
// =====================================================================
__global__ void __launch_bounds__(256) k_spmm_wide()
{
    int lane = threadIdx.x & 31;
    int n = (blockIdx.x * blockDim.x + threadIdx.x) >> 5;
    if (n >= NN) return;
    int s0 = g_rowptr[n], s1 = g_rowptr[n + 1];
    const uint2* Hp = reinterpret_cast<const uint2*>(g_Hh);
    float4 acc = make_float4(0.f, 0.f, 0.f, 0.f);
    int e = s0;
    for (; e + 4 <= s1; e += 4) {
        int2 p0 = g_edge[e],     p1 = g_edge[e + 1];
        int2 p2 = g_edge[e + 2], p3 = g_edge[e + 3];
        float v0 = __int_as_float(p0.y), v1 = __int_as_float(p1.y);
        float v2 = __int_as_float(p2.y), v3 = __int_as_float(p3.y);
        uint2 r0 = __ldg(Hp + (size_t)p0.x * 32 + lane);
        uint2 r1 = __ldg(Hp + (size_t)p1.x * 32 + lane);
        uint2 r2 = __ldg(Hp + (size_t)p2.x * 32 + lane);
        uint2 r3 = __ldg(Hp + (size_t)p3.x * 32 + lane);
        float2 a0 = __half22float2(*reinterpret_cast<__half2*>(&r0.x));
        float2 b0 = __half22float2(*reinterpret_cast<__half2*>(&r0.y));
        float2 a1 = __half22float2(*reinterpret_cast<__half2*>(&r1.x));
        float2 b1 = __half22float2(*reinterpret_cast<__half2*>(&r1.y));
        float2 a2 = __half22float2(*reinterpret_cast<__half2*>(&r2.x));
        float2 b2 = __half22float2(*reinterpret_cast<__half2*>(&r2.y));
        float2 a3 = __half22float2(*reinterpret_cast<__half2*>(&r3.x));
        float2 b3 = __half22float2(*reinterpret_cast<__half2*>(&r3.y));
        acc.x = fmaf(v0, a0.x, acc.x); acc.y = fmaf(v0, a0.y, acc.y);
        acc.z = fmaf(v0, b0.x, acc.z); acc.w = fmaf(v0, b0.y, acc.w);
        acc.x = fmaf(v1, a1.x, acc.x); acc.y = fmaf(v1, a1.y, acc.y);
        acc.z = fmaf(v1, b1.x, acc.z); acc.w = fmaf(v1, b1.y, acc.w);
        acc.x = fmaf(v2, a2.x, acc.x); acc.y = fmaf(v2, a2.y, acc.y);
        acc.z = fmaf(v2, b2.x, acc.z); acc.w = fmaf(v2, b2.y, acc.w);
        acc.x = fmaf(v3, a3.x, acc.x); acc.y = fmaf(v3, a3.y, acc.y);
        acc.z = fmaf(v3, b3.x, acc.z); acc.w = fmaf(v3, b3.y, acc.w);
    }
    for (; e < s1; e++) {
        int2 p = g_edge[e];
        float v = __int_as_float(p.y);
        uint2 r0 = __ldg(Hp + (size_t)p.x * 32 + lane);
        float2 a0 = __half22float2(*reinterpret_cast<__half2*>(&r0.x));
        float2 b0 = __half22float2(*reinterpret_cast<__half2*>(&r0.y));
        acc.x = fmaf(v, a0.x, acc.x); acc.y = fmaf(v, a0.y, acc.y);
        acc.z = fmaf(v, b0.x, acc.z); acc.w = fmaf(v, b0.y, acc.w);
    }
    reinterpret_cast<float4*>(g_Hm)[(size_t)n * 32 + lane] = acc;
}

// =====================================================================
// K3: mz = Hm @ Wm2   [N,128]@[128,128]  (proven R6 tiling)
// =====================================================================
#define HS_STRIDE 132
#define MM_SMEM   ((64 * HS_STRIDE + 32 * 128) * 4)   // 50176 bytes

__global__ void __launch_bounds__(256) k_mm()
{
    extern __shared__ float dsm[];
    float* Hs = dsm;                     // [64][132]
    float* Wt = dsm + 64 * HS_STRIDE;    // [32][128]
    int tid  = threadIdx.x;
    int base = blockIdx.x * 64;

    for (int i = tid; i < 64 * 128; i += 256) {
        int r = i >> 7, k = i & 127;
        int row = base + r;
        Hs[r * HS_STRIDE + k] = (row < NN) ? g_Hm[(size_t)row * 128 + k] : 0.f;
    }

    const int tx = tid & 15;
    const int ty = tid >> 4;
    const int j0 = tx * 4;
    const int r0 = ty * 4;
    float acc[4][8];
    #pragma unroll
    for (int r = 0; r < 4; r++)
        #pragma unroll
        for (int c = 0; c < 8; c++) acc[r][c] = 0.f;

    for (int k0 = 0; k0 < 128; k0 += 32) {
        __syncthreads();
        for (int i = tid; i < 32 * 128; i += 256)
            Wt[i] = g_Wm2[(size_t)(k0 + (i >> 7)) * 128 + (i & 127)];
        __syncthreads();
        #pragma unroll
        for (int kk = 0; kk < 32; kk++) {
            float4 wa = *reinterpret_cast<const float4*>(&Wt[kk * 128 + j0]);
            float4 wb = *reinterpret_cast<const float4*>(&Wt[kk * 128 + 64 + j0]);
            #pragma unroll
            for (int r = 0; r < 4; r++) {
                float h = Hs[(r0 + r) * HS_STRIDE + k0 + kk];
                acc[r][0] = fmaf(h, wa.x, acc[r][0]);
                acc[r][1] = fmaf(h, wa.y, acc[r][1]);
                acc[r][2] = fmaf(h, wa.z, acc[r][2]);
                acc[r][3] = fmaf(h, wa.w, acc[r][3]);
                acc[r][4] = fmaf(h, wb.x, acc[r][4]);
                acc[r][5] = fmaf(h, wb.y, acc[r][5]);
                acc[r][6] = fmaf(h, wb.z, acc[r][6]);
                acc[r][7] = fmaf(h, wb.w, acc[r][7]);
            }
        }
    }
    #pragma unroll
    for (int r = 0; r < 4; r++) {
        int row = base + r0 + r;
        if (row < NN) {
            float4 oa = make_float4(acc[r][0], acc[r][1], acc[r][2], acc[r][3]);
            float4 ob = make_float4(acc[r][4], acc[r][5], acc[r][6], acc[r][7]);
            *reinterpret_cast<float4*>(&g_mz[(size_t)row * 128 + j0])      = oa;
            *reinterpret_cast<float4*>(&g_mz[(size_t)row * 128 + 64 + j0]) = ob;
        }
    }
}

// =====================================================================
// K5: fused epilogue (proven R10 scalar form).
// Warp per node-PAIR, lane per concept.
// =====================================================================
#define OFF_W1   0
#define OFF_W2   4224
#define OFF_CST  8448
#define OFF_AT   12672
#define OFF_WREC 16896
#define OFF_BZ2  21120
#define OFF_BL2  21248
#define OFF_BREC 21280
#define OFF_ZBUF 21312                    // 8 warps * 2 nodes * 132
#define OFF_LAB  (21312 + 8 * 264)        // 8 warps * 2 nodes * 32
#define SMEM_FLOATS (OFF_LAB + 8 * 64)    // 23936 floats = 95744 bytes

__global__ void __launch_bounds__(256) k_epi(
    const float* __restrict__ label, const float* __restrict__ noise,
    const float* __restrict__ A,
    const float* __restrict__ Wz1, const float* __restrict__ bz1,
    const float* __restrict__ Wz2, const float* __restrict__ bz2,
    const float* __restrict__ Wl1, const float* __restrict__ bl1,
    const float* __restrict__ Wl2, const float* __restrict__ bl2,
    const float* __restrict__ Wrec, const float* __restrict__ brec,
    float* __restrict__ out_rec, float* __restrict__ out_pred)
{
    extern __shared__ float sm[];
    int tid = threadIdx.x;

    for (int i = tid; i < 4096; i += 256) {
        int c = i >> 7, r = i & 127, g = r >> 2, d = r & 3;
        sm[OFF_W1 + c * 132 + g * 4 + d] = Wz1[c * 128 + d * 32 + g];
        sm[OFF_W2 + c * 132 + g * 4 + d] = Wz2[c * 128 + g * 4 + d];
        int k = i >> 5, j = i & 31;
        sm[OFF_WREC + j * 132 + k] = Wrec[k * 32 + j];
    }
    for (int i = tid; i < 1024; i += 256) {
        int k = i >> 5, c = i & 31;
        sm[OFF_AT + c * 132 + k] = A[k * 32 + c];
        int cc = i >> 5, g = i & 31;
        float* p = sm + OFF_CST + cc * 132 + g * 4;
        p[0] = bz1[cc * 32 + g];
        p[1] = Wl1[cc * 32 + g];
        p[2] = bl1[cc * 32 + g];
        p[3] = Wl2[cc * 32 + g];
    }
    for (int i = tid; i < 128; i += 256) sm[OFF_BZ2 + i] = bz2[i];
    if (tid < 32) { sm[OFF_BL2 + tid] = bl2[tid]; sm[OFF_BREC + tid] = brec[tid]; }
    __syncthreads();

    const int warp = tid >> 5;
    const int lane = tid & 31;
    unsigned gw = blockIdx.x * 8 + warp;
    unsigned nwrp = gridDim.x * 8;

    float* zbA = sm + OFF_ZBUF + warp * 264;
    float* zbB = zbA + 132;
    float* lbA = sm + OFF_LAB + warp * 64;
    float* lbB = lbA + 32;
    const float* w1p = sm + OFF_W1   + lane * 132;
    const float* w2p = sm + OFF_W2   + lane * 132;
    const float* csp = sm + OFF_CST  + lane * 132;
    const float* atp = sm + OFF_AT   + lane * 132;
    const float* wrp = sm + OFF_WREC + lane * 132;
    const float  SQL = 0.0316227766016838f;   // sqrt(1e-3)

    // NN is even: pair (n, n+1) always valid when n < NN
    for (unsigned n = gw * 2; n < NN; n += nwrp * 2) {
        unsigned nA = n, nB = n + 1;
        float4 mzA = *reinterpret_cast<const float4*>(g_mz + (size_t)nA * 128 + lane * 4);
        float4 mzB = *reinterpret_cast<const float4*>(g_mz + (size_t)nB * 128 + lane * 4);
        float4 nzA = __ldg(reinterpret_cast<const float4*>(noise + (size_t)nA * 128) + lane);
        float4 nzB = __ldg(reinterpret_cast<const float4*>(noise + (size_t)nB * 128) + lane);
        lbA[lane] = __ldg(label + (size_t)nA * 32 + lane);
        lbB[lane] = __ldg(label + (size_t)nB * 32 + lane);
        __syncwarp();

        float mlA = 0.f, mlB = 0.f;
        #pragma unroll
        for (int k = 0; k < 32; k += 4) {
            float4 a4 = *reinterpret_cast<const float4*>(atp + k);
            float4 lA = *reinterpret_cast<const float4*>(lbA + k);
            float4 lB = *reinterpret_cast<const float4*>(lbB + k);
            mlA = fmaf(lA.x, a4.x, mlA); mlA = fmaf(lA.y, a4.y, mlA);
            mlA = fmaf(lA.z, a4.z, mlA); mlA = fmaf(lA.w, a4.w, mlA);
            mlB = fmaf(lB.x, a4.x, mlB); mlB = fmaf(lB.y, a4.y, mlB);
            mlB = fmaf(lB.z, a4.z, mlB); mlB = fmaf(lB.w, a4.w, mlB);
        }

        float4 z2A = *reinterpret_cast<const float4*>(sm + OFF_BZ2 + lane * 4);
        float4 z2B = z2A;
        float predA = sm[OFF_BL2 + lane];
        float predB = predA;

        #pragma unroll 4
        for (int g = 0; g < 32; g++) {
            float4 w1 = *reinterpret_cast<const float4*>(w1p + g * 4);
            float4 cs = *reinterpret_cast<const float4*>(csp + g * 4);
            float4 w2 = *reinterpret_cast<const float4*>(w2p + g * 4);

            float tA = cs.x;
            tA = fmaf(mzA.x, w1.x, tA); tA = fmaf(mzA.y, w1.y, tA);
            tA = fmaf(mzA.z, w1.z, tA); tA = fmaf(mzA.w, w1.w, tA);
            float hzA = tA > 0.f ? tA : (__expf(tA) - 1.f);
            z2A.x = fmaf(hzA, w2.x, z2A.x); z2A.y = fmaf(hzA, w2.y, z2A.y);
            z2A.z = fmaf(hzA, w2.z, z2A.z); z2A.w = fmaf(hzA, w2.w, z2A.w);

            float tB = cs.x;
            tB = fmaf(mzB.x, w1.x, tB); tB = fmaf(mzB.y, w1.y, tB);
            tB = fmaf(mzB.z, w1.z, tB); tB = fmaf(mzB.w, w1.w, tB);
            float hzB = tB > 0.f ? tB : (__expf(tB) - 1.f);
            z2B.x = fmaf(hzB, w2.x, z2B.x); z2B.y = fmaf(hzB, w2.y, z2B.y);
            z2B.z = fmaf(hzB, w2.z, z2B.z); z2B.w = fmaf(hzB, w2.w, z2B.w);

            float tlA = fmaf(mlA, cs.y, cs.z);
            float hlA = tlA > 0.f ? tlA : (__expf(tlA) - 1.f);
            predA = fmaf(hlA, cs.w, predA);
            float tlB = fmaf(mlB, cs.y, cs.z);
            float hlB = tlB > 0.f ? tlB : (__expf(tlB) - 1.f);
            predB = fmaf(hlB, cs.w, predB);
        }

        float4 zA, zB;
        zA.x = fmaf(SQL, nzA.x, z2A.x); zA.y = fmaf(SQL, nzA.y, z2A.y);
        zA.z = fmaf(SQL, nzA.z, z2A.z); zA.w = fmaf(SQL, nzA.w, z2A.w);
        zB.x = fmaf(SQL, nzB.x, z2B.x); zB.y = fmaf(SQL, nzB.y, z2B.y);
        zB.z = fmaf(SQL, nzB.z, z2B.z); zB.w = fmaf(SQL, nzB.w, z2B.w);
        *reinterpret_cast<float4*>(zbA + lane * 4) = zA;
        *reinterpret_cast<float4*>(zbB + lane * 4) = zB;
        __syncwarp();

        float accA = sm[OFF_BREC + lane];
        float accB = accA;
        #pragma unroll
        for (int k = 0; k < 128; k += 4) {
            float4 wr = *reinterpret_cast<const float4*>(wrp + k);
            float4 vA = *reinterpret_cast<const float4*>(zbA + k);
            float4 vB = *reinterpret_cast<const float4*>(zbB + k);
            accA = fmaf(vA.x, wr.x, accA); accA = fmaf(vA.y, wr.y, accA);
            accA = fmaf(vA.z, wr.z, accA); accA = fmaf(vA.w, wr.w, accA);
            accB = fmaf(vB.x, wr.x, accB); accB = fmaf(vB.y, wr.y, accB);
            accB = fmaf(vB.z, wr.z, accB); accB = fmaf(vB.w, wr.w, accB);
        }
        out_rec[(size_t)nA * 32 + lane]  = accA;
        out_rec[(size_t)nB * 32 + lane]  = accB;
        out_pred[(size_t)nA * 32 + lane] = predA;
        out_pred[(size_t)nB * 32 + lane] = predB;
        __syncwarp();
    }
}

// =====================================================================
// launch
// =====================================================================
extern "C" void kernel_launch(void* const* d_in, const int* in_sizes, int n_in,
                              void* d_out, int out_size)
{
    const float* X      = (const float*)d_in[0];
    const float* label  = (const float*)d_in[1];
    const float* eval_  = (const float*)d_in[2];
    const float* noise  = (const float*)d_in[3];
    const float* Wb     = (const float*)d_in[4];
    const float* Wm     = (const float*)d_in[5];
    // d_in[6] = W_logstd -> result discarded in reference, skipped entirely
    const float* A      = (const float*)d_in[7];
    const float* Wz1    = (const float*)d_in[8];
    const float* bz1    = (const float*)d_in[9];
    const float* Wz2    = (const float*)d_in[10];
    const float* bz2    = (const float*)d_in[11];
    const float* Wl1    = (const float*)d_in[12];
    const float* bl1    = (const float*)d_in[13];
    const float* Wl2    = (const float*)d_in[14];
    const float* bl2    = (const float*)d_in[15];
    const float* Wrec   = (const float*)d_in[16];
    const float* brec   = (const float*)d_in[17];
    const int*   esrc   = (const int*)d_in[18];
    const int*   edst   = (const int*)d_in[19];

    float* out_rec  = (float*)d_out;
    float* out_pred = out_rec + (size_t)NN * 32;

    cudaFuncSetAttribute(k_epi, cudaFuncAttributeMaxDynamicSharedMemorySize,
                         SMEM_FLOATS * (int)sizeof(float));
    cudaFuncSetAttribute(k_mm, cudaFuncAttributeMaxDynamicSharedMemorySize,
                         MM_SMEM);

    // tiny weight prep + X fp16 conversion
    k_prep<<<1, dim3(32, 32)>>>(A);
    k_fold<<<64, 256>>>(Wm);
    k_xcvt<<<800, 256>>>(X);

    // counting sort of edges by dst -> CSR (paired {src, val})
    k_zero_deg<<<(NN + 255) / 256, 256>>>();
    k_hist<<<2048, 256>>>(edst);
    k_scan1<<<SCAN_BLOCKS, SCAN_TPB>>>();
    k_scan2<<<1, 32>>>();
    k_scan3<<<(NN + 256) / 256, 256>>>();
    k_scatter<<<2048, 256>>>(esrc, edst, eval_);

    // main pipeline
    k_enc<<<1536, 256>>>(Wb);                           // H = relu(spmm(Xh) @ Wb), fp16
    k_spmm_wide<<<(NN * 32 + 255) / 256, 256>>>();      // Hm = spmm(H)  (fp32 accum)
    k_mm<<<(NN + 63) / 64, 256, MM_SMEM>>>();           // mz = Hm @ Wm2
    k_epi<<<296, 256, SMEM_FLOATS * sizeof(float)>>>(
        label, noise, A, Wz1, bz1, Wz2, bz2, Wl1, bl1, Wl2, bl2,
        Wrec, brec, out_rec, out_pred);
}

// round 15
// speedup vs baseline: 1.0427x; 1.0183x over previous
#include <cuda_runtime.h>
#include <cuda_fp16.h>
#include <cstdint>

// Problem constants (fixed by the dataset)
#define NN   100000
#define EE   1600000
#define INF  32
#define HH   128
#define CC   32
#define DD   4
#define GG   32

#define SCAN_TPB    512
#define SCAN_ELEMS  1024
#define SCAN_BLOCKS 98     // ceil(NN / 1024)

// -------- scratch (no cudaMalloc allowed) --------
__device__ int   g_deg[NN];
__device__ int   g_cur[NN];
__device__ int   g_rowptr[NN + 2];
__device__ int   g_part[SCAN_BLOCKS];
__device__ int2  g_edge[EE];              // {src, float_bits(val)} sorted by dst

__device__ __half g_Hh[(size_t)NN * HH];  // relu(spmm(X)@Wb), fp16 [N,128]
__device__ float g_Hm[(size_t)NN * HH];   // spmm(H)                [N,128]
__device__ float g_mz[(size_t)NN * HH];   // Hm @ Wm2 = masked_z
__device__ float g_M2[CC * CC];           // A^T (I - A^T)^{-1}
__device__ float g_Wm2[HH * HH];          // folded W_mean

// =====================================================================
// K0a: M2 = A^T @ inv(I - A^T).  One 32x32 block.
// =====================================================================
__global__ void k_prep(const float* __restrict__ A)
{
    __shared__ float B[32][33];
    __shared__ float Inv[32][33];
    int cc = threadIdx.x;
    int r  = threadIdx.y;
    B[r][cc]   = (r == cc ? 1.f : 0.f) - A[cc * 32 + r];
    Inv[r][cc] = (r == cc ? 1.f : 0.f);
    __syncthreads();

    for (int k = 0; k < 32; k++) {
        float piv = B[k][k];
        __syncthreads();
        if (r == k) {
            float inv = 1.f / piv;
            B[k][cc]   *= inv;
            Inv[k][cc] *= inv;
        }
        __syncthreads();
        float f  = B[r][k];
        float bk = B[k][cc];
        float ik = Inv[k][cc];
        __syncthreads();
        if (r != k) {
            B[r][cc]   -= f * bk;
            Inv[r][cc] -= f * ik;
        }
        __syncthreads();
    }
    float acc = 0.f;
    #pragma unroll
    for (int j = 0; j < 32; j++)
        acc += A[j * 32 + r] * Inv[j][cc];
    g_M2[r * 32 + cc] = acc;
}

// =====================================================================
// K0b: Wm2[h, c*4+d] = sum_k M2[c,k] * Wm[h, k*4+d]
// =====================================================================
__global__ void k_fold(const float* __restrict__ Wm)
{
    int idx = blockIdx.x * blockDim.x + threadIdx.x;
    int h  = idx >> 7;
    int cd = idx & 127;
    int c  = cd >> 2;
    int d  = cd & 3;
    float acc = 0.f;
    #pragma unroll
    for (int k = 0; k < 32; k++)
        acc += g_M2[c * 32 + k] * Wm[h * 128 + k * 4 + d];
    g_Wm2[h * 128 + cd] = acc;
}

// =====================================================================
// Counting sort of edges by dst
// =====================================================================
__global__ void k_zero_deg()
{
    int i = blockIdx.x * blockDim.x + threadIdx.x;
    if (i < NN) g_deg[i] = 0;
}

__global__ void k_hist(const int* __restrict__ dst)
{
    int i = blockIdx.x * blockDim.x + threadIdx.x;
    int stride = gridDim.x * blockDim.x;
    for (int e = i; e < EE; e += stride)
        atomicAdd(&g_deg[__ldg(dst + e)], 1);
}

__global__ void k_scan1()
{
    __shared__ int wsum[16];
    int tid  = threadIdx.x;
    int base = blockIdx.x * SCAN_ELEMS;
    int i0   = base + 2 * tid;
    int a = (i0     < NN) ? g_deg[i0]     : 0;
    int b = (i0 + 1 < NN) ? g_deg[i0 + 1] : 0;
    int s = a + b;
    int lane = tid & 31, w = tid >> 5;
    int incl = s;
    #pragma unroll
    for (int d = 1; d < 32; d <<= 1) {
        int t = __shfl_up_sync(0xffffffff, incl, d);
        if (lane >= d) incl += t;
    }
    if (lane == 31) wsum[w] = incl;
    __syncthreads();
    if (tid < 16) {
        int v = wsum[tid];
        int iv = v;
        #pragma unroll
        for (int d = 1; d < 16; d <<= 1) {
            int t = __shfl_up_sync(0xffff, iv, d);
            if (tid >= d) iv += t;
        }
        wsum[tid] = iv - v;
    }
    __syncthreads();
    int excl = wsum[w] + incl - s;
    if (i0 <= NN)     g_rowptr[i0]     = excl;
    if (i0 + 1 <= NN) g_rowptr[i0 + 1] = excl + a;
    if (tid == SCAN_TPB - 1) g_part[blockIdx.x] = excl + s;
}

__global__ void k_scan2()
{
    if (threadIdx.x == 0) {
        int run = 0;
        for (int i = 0; i < SCAN_BLOCKS; i++) {
            int v = g_part[i];
            g_part[i] = run;
            run += v;
        }
    }
}

__global__ void k_scan3()
{
    int i = blockIdx.x * blockDim.x + threadIdx.x;
    if (i <= NN) {
        int r = g_rowptr[i] + g_part[i >> 10];
        g_rowptr[i] = r;
        if (i < NN) g_cur[i] = r;
    }
}

__global__ void k_scatter(const int* __restrict__ src,
                          const int* __restrict__ dst,
                          const float* __restrict__ val)
{
    int i = blockIdx.x * blockDim.x + threadIdx.x;
    int stride = gridDim.x * blockDim.x;
    for (int e = i; e < EE; e += stride) {
        int d = __ldg(dst + e);
        int pos = atomicAdd(&g_cur[d], 1);
        g_edge[pos] = make_int2(__ldg(src + e), __float_as_int(__ldg(val + e)));
    }
}

// =====================================================================
// k_enc: fused  T = spmm(X) ;  H = relu(T @ W_base), stored fp16
// warp per node (grid-stride). 8-deep load batches for MLP.
// =====================================================================
__global__ void __launch_bounds__(256) k_enc(const float* __restrict__ X,
                                             const float* __restrict__ Wb)
{
    __shared__ float Ws[32 * 128];   // W_base, row-major [k][j]
    __shared__ float Ts[8][34];      // per-warp T broadcast buffer
    int tid = threadIdx.x;
    for (int i = tid; i < 32 * 128; i += 256) Ws[i] = Wb[i];
    __syncthreads();

    const int lane = tid & 31;
    const int warp = tid >> 5;
    unsigned gw = blockIdx.x * 8 + warp;
    unsigned nw = gridDim.x * 8;
    const float4* Ws4 = reinterpret_cast<const float4*>(Ws);

    for (unsigned n = gw; n < NN; n += nw) {
        int s0 = g_rowptr[n], s1 = g_rowptr[n + 1];
        float acc = 0.f;
        int e = s0;
        for (; e + 8 <= s1; e += 8) {
            int2 p[8];
            #pragma unroll
            for (int j = 0; j < 8; j++) p[j] = g_edge[e + j];
            float x[8];
            #pragma unroll
            for (int j = 0; j < 8; j++)
                x[j] = __ldg(X + (size_t)p[j].x * 32 + lane);
            #pragma unroll
            for (int j = 0; j < 8; j++)
                acc = fmaf(__int_as_float(p[j].y), x[j], acc);
        }
        for (; e + 4 <= s1; e += 4) {
            int2 p[4];
            #pragma unroll
            for (int j = 0; j < 4; j++) p[j] = g_edge[e + j];
            float x[4];
            #pragma unroll
            for (int j = 0; j < 4; j++)
                x[j] = __ldg(X + (size_t)p[j].x * 32 + lane);
            #pragma unroll
            for (int j = 0; j < 4; j++)
                acc = fmaf(__int_as_float(p[j].y), x[j], acc);
        }
        for (; e < s1; e++) {
            int2 p = g_edge[e];
            acc = fmaf(__int_as_float(p.y), __ldg(X + (size_t)p.x * 32 + lane), acc);
        }
        Ts[warp][lane] = acc;
        __syncwarp();

        float4 h = make_float4(0.f, 0.f, 0.f, 0.f);
        #pragma unroll
        for (int k = 0; k < 32; k++) {
            float tk = Ts[warp][k];
            float4 wv = Ws4[k * 32 + lane];
            h.x = fmaf(tk, wv.x, h.x); h.y = fmaf(tk, wv.y, h.y);
            h.z = fmaf(tk, wv.z, h.z); h.w = fmaf(tk, wv.w, h.w);
        }
        h.x = h.x > 0.f ? h.x : 0.f; h.y = h.y > 0.f ? h.y : 0.f;
        h.z = h.z > 0.f ? h.z : 0.f; h.w = h.w > 0.f ? h.w : 0.f;
        __half2 a = __floats2half2_rn(h.x, h.y);
        __half2 b = __floats2half2_rn(h.z, h.w);
        uint2 pk;
        pk.x = *reinterpret_cast<unsigned*>(&a);
        pk.y = *reinterpret_cast<unsigned*>(&b);
        reinterpret_cast<uint2*>(g_Hh)[(size_t)n * 32 + lane] = pk;
        __syncwarp();
    }
}

// =====================================================================
// spmm wide: Hm[n,:128] = sum_{e in row n} val[e] * H[src[e], :128]
// warp per node, lane handles 4 columns (fp16x4 = 8B load per edge).
// 8-deep front-batched load groups for MLP. fp32 accumulation.
// =====================================================================
__global__ void __launch_bounds__(256) k_spmm_wide()
{
    int lane = threadIdx.x & 31;
    int n = (blockIdx.x * blockDim.x + threadIdx.x) >> 5;
    if (n >= NN) return;
    int s0 = g_rowptr[n], s1 = g_rowptr[n + 1];
    const uint2* Hp = reinterpret_cast<const uint2*>(g_Hh);
    float4 acc = make_float4(0.f, 0.f, 0.f, 0.f);
    int e = s0;
    for (; e + 8 <= s1; e += 8) {
        int2 p[8];
        #pragma unroll
        for (int j = 0; j < 8; j++) p[j] = g_edge[e + j];
        uint2 r[8];
        #pragma unroll
        for (int j = 0; j < 8; j++)
            r[j] = __ldg(Hp + (size_t)p[j].x * 32 + lane);
        #pragma unroll
        for (int j = 0; j < 8; j++) {
            float v = __int_as_float(p[j].y);
            float2 a0 = __half22float2(*reinterpret_cast<__half2*>(&r[j].x));
            float2 b0 = __half22float2(*reinterpret_cast<__half2*>(&r[j].y));
            acc.x = fmaf(v, a0.x, acc.x); acc.y = fmaf(v, a0.y, acc.y);
            acc.z = fmaf(v, b0.x, acc.z); acc.w = fmaf(v, b0.y, acc.w);
        }
    }
    for (; e + 4 <= s1; e += 4) {
        int2 p[4];
        #pragma unroll
        for (int j = 0; j < 4; j++) p[j] = g_edge[e + j];
        uint2 r[4];
        #pragma unroll
        for (int j = 0; j < 4; j++)
            r[j] = __ldg(Hp + (size_t)p[j].x * 32 + lane);
        #pragma unroll
        for (int j = 0; j < 4; j++) {
            float v = __int_as_float(p[j].y);
            float2 a0 = __half22float2(*reinterpret_cast<__half2*>(&r[j].x));
            float2 b0 = __half22float2(*reinterpret_cast<__half2*>(&r[j].y));
            acc.x = fmaf(v, a0.x, acc.x); acc.y = fmaf(v, a0.y, acc.y);
            acc.z = fmaf(v, b0.x, acc.z); acc.w = fmaf(v, b0.y, acc.w);
        }
    }
    for (; e < s1; e++) {
        int2 p = g_edge[e];
        float v = __int_as_float(p.y);
        uint2 r0 = __ldg(Hp + (size_t)p.x * 32 + lane);
        float2 a0 = __half22float2(*reinterpret_cast<__half2*>(&r0.x));
        float2 b0 = __half22float2(*reinterpret_cast<__half2*>(&r0.y));
        acc.x = fmaf(v, a0.x, acc.x); acc.y = fmaf(v, a0.y, acc.y);
        acc.z = fmaf(v, b0.x, acc.z); acc.w = fmaf(v, b0.y, acc.w);
    }
    reinterpret_cast<float4*>(g_Hm)[(size_t)n * 32 + lane] = acc;
}

// =====================================================================
// K3: mz = Hm @ Wm2   [N,128]@[128,128]  (proven R6 tiling)
// =====================================================================
#define HS_STRIDE 132
#define MM_SMEM   ((64 * HS_STRIDE + 32 * 128) * 4)   // 50176 bytes

__global__ void __launch_bounds__(256) k_mm()
{
    extern __shared__ float dsm[];
    float* Hs = dsm;                     // [64][132]
    float* Wt = dsm + 64 * HS_STRIDE;    // [32][128]
    int tid  = threadIdx.x;
    int base = blockIdx.x * 64;

    for (int i = tid; i < 64 * 128; i += 256) {
        int r = i >> 7, k = i & 127;
        int row = base + r;
        Hs[r * HS_STRIDE + k] = (row < NN) ? g_Hm[(size_t)row * 128 + k] : 0.f;
    }

    const int tx = tid & 15;
    const int ty = tid >> 4;
    const int j0 = tx * 4;
    const int r0 = ty * 4;
    float acc[4][8];
    #pragma unroll
    for (int r = 0; r < 4; r++)
        #pragma unroll
        for (int c = 0; c < 8; c++) acc[r][c] = 0.f;

    for (int k0 = 0; k0 < 128; k0 += 32) {
        __syncthreads();
        for (int i = tid; i < 32 * 128; i += 256)
            Wt[i] = g_Wm2[(size_t)(k0 + (i >> 7)) * 128 + (i & 127)];
        __syncthreads();
        #pragma unroll
        for (int kk = 0; kk < 32; kk++) {
            float4 wa = *reinterpret_cast<const float4*>(&Wt[kk * 128 + j0]);
            float4 wb = *reinterpret_cast<const float4*>(&Wt[kk * 128 + 64 + j0]);
            #pragma unroll
            for (int r = 0; r < 4; r++) {
                float h = Hs[(r0 + r) * HS_STRIDE + k0 + kk];
                acc[r][0] = fmaf(h, wa.x, acc[r][0]);
                acc[r][1] = fmaf(h, wa.y, acc[r][1]);
                acc[r][2] = fmaf(h, wa.z, acc[r][2]);
                acc[r][3] = fmaf(h, wa.w, acc[r][3]);
                acc[r][4] = fmaf(h, wb.x, acc[r][4]);
                acc[r][5] = fmaf(h, wb.y, acc[r][5]);
                acc[r][6] = fmaf(h, wb.z, acc[r][6]);
                acc[r][7] = fmaf(h, wb.w, acc[r][7]);
            }
        }
    }
    #pragma unroll
    for (int r = 0; r < 4; r++) {
        int row = base + r0 + r;
        if (row < NN) {
            float4 oa = make_float4(acc[r][0], acc[r][1], acc[r][2], acc[r][3]);
            float4 ob = make_float4(acc[r][4], acc[r][5], acc[r][6], acc[r][7]);
            *reinterpret_cast<float4*>(&g_mz[(size_t)row * 128 + j0])      = oa;
            *reinterpret_cast<float4*>(&g_mz[(size_t)row * 128 + 64 + j0]) = ob;
        }
    }
}

// =====================================================================
// K5: fused epilogue (proven R10 scalar form).
// Warp per node-PAIR, lane per concept.
// =====================================================================
#define OFF_W1   0
#define OFF_W2   4224
#define OFF_CST  8448
#define OFF_AT   12672
#define OFF_WREC 16896
#define OFF_BZ2  21120
#define OFF_BL2  21248
#define OFF_BREC 21280
#define OFF_ZBUF 21312                    // 8 warps * 2 nodes * 132
#define OFF_LAB  (21312 + 8 * 264)        // 8 warps * 2 nodes * 32
#define SMEM_FLOATS (OFF_LAB + 8 * 64)    // 23936 floats = 95744 bytes

__global__ void __launch_bounds__(256) k_epi(
    const float* __restrict__ label, const float* __restrict__ noise,
    const float* __restrict__ A,
    const float* __restrict__ Wz1, const float* __restrict__ bz1,
    const float* __restrict__ Wz2, const float* __restrict__ bz2,
    const float* __restrict__ Wl1, const float* __restrict__ bl1,
    const float* __restrict__ Wl2, const float* __restrict__ bl2,
    const float* __restrict__ Wrec, const float* __restrict__ brec,
    float* __restrict__ out_rec, float* __restrict__ out_pred)
{
    extern __shared__ float sm[];
    int tid = threadIdx.x;

    for (int i = tid; i < 4096; i += 256) {
        int c = i >> 7, r = i & 127, g = r >> 2, d = r & 3;
        sm[OFF_W1 + c * 132 + g * 4 + d] = Wz1[c * 128 + d * 32 + g];
        sm[OFF_W2 + c * 132 + g * 4 + d] = Wz2[c * 128 + g * 4 + d];
        int k = i >> 5, j = i & 31;
        sm[OFF_WREC + j * 132 + k] = Wrec[k * 32 + j];
    }
    for (int i = tid; i < 1024; i += 256) {
        int k = i >> 5, c = i & 31;
        sm[OFF_AT + c * 132 + k] = A[k * 32 + c];
        int cc = i >> 5, g = i & 31;
        float* p = sm + OFF_CST + cc * 132 + g * 4;
        p[0] = bz1[cc * 32 + g];
        p[1] = Wl1[cc * 32 + g];
        p[2] = bl1[cc * 32 + g];
        p[3] = Wl2[cc * 32 + g];
    }
    for (int i = tid; i < 128; i += 256) sm[OFF_BZ2 + i] = bz2[i];
    if (tid < 32) { sm[OFF_BL2 + tid] = bl2[tid]; sm[OFF_BREC + tid] = brec[tid]; }
    __syncthreads();

    const int warp = tid >> 5;
    const int lane = tid & 31;
    unsigned gw = blockIdx.x * 8 + warp;
    unsigned nwrp = gridDim.x * 8;

    float* zbA = sm + OFF_ZBUF + warp * 264;
    float* zbB = zbA + 132;
    float* lbA = sm + OFF_LAB + warp * 64;
    float* lbB = lbA + 32;
    const float* w1p = sm + OFF_W1   + lane * 132;
    const float* w2p = sm + OFF_W2   + lane * 132;
    const float* csp = sm + OFF_CST  + lane * 132;
    const float* atp = sm + OFF_AT   + lane * 132;
    const float* wrp = sm + OFF_WREC + lane * 132;
    const float  SQL = 0.0316227766016838f;   // sqrt(1e-3)

    // NN is even: pair (n, n+1) always valid when n < NN
    for (unsigned n = gw * 2; n < NN; n += nwrp * 2) {
        unsigned nA = n, nB = n + 1;
        float4 mzA = *reinterpret_cast<const float4*>(g_mz + (size_t)nA * 128 + lane * 4);
        float4 mzB = *reinterpret_cast<const float4*>(g_mz + (size_t)nB * 128 + lane * 4);
        float4 nzA = __ldg(reinterpret_cast<const float4*>(noise + (size_t)nA * 128) + lane);
        float4 nzB = __ldg(reinterpret_cast<const float4*>(noise + (size_t)nB * 128) + lane);
        lbA[lane] = __ldg(label + (size_t)nA * 32 + lane);
        lbB[lane] = __ldg(label + (size_t)nB * 32 + lane);
        __syncwarp();

        float mlA = 0.f, mlB = 0.f;
        #pragma unroll
        for (int k = 0; k < 32; k += 4) {
            float4 a4 = *reinterpret_cast<const float4*>(atp + k);
            float4 lA = *reinterpret_cast<const float4*>(lbA + k);
            float4 lB = *reinterpret_cast<const float4*>(lbB + k);
            mlA = fmaf(lA.x, a4.x, mlA); mlA = fmaf(lA.y, a4.y, mlA);
            mlA = fmaf(lA.z, a4.z, mlA); mlA = fmaf(lA.w, a4.w, mlA);
            mlB = fmaf(lB.x, a4.x, mlB); mlB = fmaf(lB.y, a4.y, mlB);
            mlB = fmaf(lB.z, a4.z, mlB); mlB = fmaf(lB.w, a4.w, mlB);
        }

        float4 z2A = *reinterpret_cast<const float4*>(sm + OFF_BZ2 + lane * 4);
        float4 z2B = z2A;
        float predA = sm[OFF_BL2 + lane];
        float predB = predA;

        #pragma unroll 4
        for (int g = 0; g < 32; g++) {
            float4 w1 = *reinterpret_cast<const float4*>(w1p + g * 4);
            float4 cs = *reinterpret_cast<const float4*>(csp + g * 4);
            float4 w2 = *reinterpret_cast<const float4*>(w2p + g * 4);

            float tA = cs.x;
            tA = fmaf(mzA.x, w1.x, tA); tA = fmaf(mzA.y, w1.y, tA);
            tA = fmaf(mzA.z, w1.z, tA); tA = fmaf(mzA.w, w1.w, tA);
            float hzA = tA > 0.f ? tA : (__expf(tA) - 1.f);
            z2A.x = fmaf(hzA, w2.x, z2A.x); z2A.y = fmaf(hzA, w2.y, z2A.y);
            z2A.z = fmaf(hzA, w2.z, z2A.z); z2A.w = fmaf(hzA, w2.w, z2A.w);

            float tB = cs.x;
            tB = fmaf(mzB.x, w1.x, tB); tB = fmaf(mzB.y, w1.y, tB);
            tB = fmaf(mzB.z, w1.z, tB); tB = fmaf(mzB.w, w1.w, tB);
            float hzB = tB > 0.f ? tB : (__expf(tB) - 1.f);
            z2B.x = fmaf(hzB, w2.x, z2B.x); z2B.y = fmaf(hzB, w2.y, z2B.y);
            z2B.z = fmaf(hzB, w2.z, z2B.z); z2B.w = fmaf(hzB, w2.w, z2B.w);

            float tlA = fmaf(mlA, cs.y, cs.z);
            float hlA = tlA > 0.f ? tlA : (__expf(tlA) - 1.f);
            predA = fmaf(hlA, cs.w, predA);
            float tlB = fmaf(mlB, cs.y, cs.z);
            float hlB = tlB > 0.f ? tlB : (__expf(tlB) - 1.f);
            predB = fmaf(hlB, cs.w, predB);
        }

        float4 zA, zB;
        zA.x = fmaf(SQL, nzA.x, z2A.x); zA.y = fmaf(SQL, nzA.y, z2A.y);
        zA.z = fmaf(SQL, nzA.z, z2A.z); zA.w = fmaf(SQL, nzA.w, z2A.w);
        zB.x = fmaf(SQL, nzB.x, z2B.x); zB.y = fmaf(SQL, nzB.y, z2B.y);
        zB.z = fmaf(SQL, nzB.z, z2B.z); zB.w = fmaf(SQL, nzB.w, z2B.w);
        *reinterpret_cast<float4*>(zbA + lane * 4) = zA;
        *reinterpret_cast<float4*>(zbB + lane * 4) = zB;
        __syncwarp();

        float accA = sm[OFF_BREC + lane];
        float accB = accA;
        #pragma unroll
        for (int k = 0; k < 128; k += 4) {
            float4 wr = *reinterpret_cast<const float4*>(wrp + k);
            float4 vA = *reinterpret_cast<const float4*>(zbA + k);
            float4 vB = *reinterpret_cast<const float4*>(zbB + k);
            accA = fmaf(vA.x, wr.x, accA); accA = fmaf(vA.y, wr.y, accA);
            accA = fmaf(vA.z, wr.z, accA); accA = fmaf(vA.w, wr.w, accA);
            accB = fmaf(vB.x, wr.x, accB); accB = fmaf(vB.y, wr.y, accB);
            accB = fmaf(vB.z, wr.z, accB); accB = fmaf(vB.w, wr.w, accB);
        }
        out_rec[(size_t)nA * 32 + lane]  = accA;
        out_rec[(size_t)nB * 32 + lane]  = accB;
        out_pred[(size_t)nA * 32 + lane] = predA;
        out_pred[(size_t)nB * 32 + lane] = predB;
        __syncwarp();
    }
}

// =====================================================================
// launch
// =====================================================================
extern "C" void kernel_launch(void* const* d_in, const int* in_sizes, int n_in,
                              void* d_out, int out_size)
{
    const float* X      = (const float*)d_in[0];
    const float* label  = (const float*)d_in[1];
    const float* eval_  = (const float*)d_in[2];
    const float* noise  = (const float*)d_in[3];
    const float* Wb     = (const float*)d_in[4];
    const float* Wm     = (const float*)d_in[5];
    // d_in[6] = W_logstd -> result discarded in reference, skipped entirely
    const float* A      = (const float*)d_in[7];
    const float* Wz1    = (const float*)d_in[8];
    const float* bz1    = (const float*)d_in[9];
    const float* Wz2    = (const float*)d_in[10];
    const float* bz2    = (const float*)d_in[11];
    const float* Wl1    = (const float*)d_in[12];
    const float* bl1    = (const float*)d_in[13];
    const float* Wl2    = (const float*)d_in[14];
    const float* bl2    = (const float*)d_in[15];
    const float* Wrec   = (const float*)d_in[16];
    const float* brec   = (const float*)d_in[17];
    const int*   esrc   = (const int*)d_in[18];
    const int*   edst   = (const int*)d_in[19];

    float* out_rec  = (float*)d_out;
    float* out_pred = out_rec + (size_t)NN * 32;

    cudaFuncSetAttribute(k_epi, cudaFuncAttributeMaxDynamicSharedMemorySize,
                         SMEM_FLOATS * (int)sizeof(float));
    cudaFuncSetAttribute(k_mm, cudaFuncAttributeMaxDynamicSharedMemorySize,
                         MM_SMEM);

    // tiny weight prep
    k_prep<<<1, dim3(32, 32)>>>(A);
    k_fold<<<64, 256>>>(Wm);

    // counting sort of edges by dst -> CSR (paired {src, val})
    k_zero_deg<<<(NN + 255) / 256, 256>>>();
    k_hist<<<2048, 256>>>(edst);
    k_scan1<<<SCAN_BLOCKS, SCAN_TPB>>>();
    k_scan2<<<1, 32>>>();
    k_scan3<<<(NN + 256) / 256, 256>>>();
    k_scatter<<<2048, 256>>>(esrc, edst, eval_);

    // main pipeline
    k_enc<<<1536, 256>>>(X, Wb);                        // H = relu(spmm(X) @ Wb), fp16
    k_spmm_wide<<<(NN * 32 + 255) / 256, 256>>>();      // Hm = spmm(H)  (fp32 accum)
    k_mm<<<(NN + 63) / 64, 256, MM_SMEM>>>();           // mz = Hm @ Wm2
    k_epi<<<296, 256, SMEM_FLOATS * sizeof(float)>>>(
        label, noise, A, Wz1, bz1, Wz2, bz2, Wl1, bl1, Wl2, bl2,
        Wrec, brec, out_rec, out_pred);
}

// round 16
// speedup vs baseline: 1.0639x; 1.0203x over previous
#include <cuda_runtime.h>
#include <cuda_fp16.h>
#include <cstdint>

// Problem constants (fixed by the dataset)
#define NN   100000
#define EE   1600000
#define INF  32
#define HH   128
#define CC   32
#define DD   4
#define GG   32

#define SCAN_TPB    512
#define SCAN_ELEMS  1024
#define SCAN_BLOCKS 98     // ceil(NN / 1024)

#define LUT_N    2048      // intervals; 2049 points, range [-8, 8], h = 1/128
#define LUT_PTS  2049

// -------- scratch (no cudaMalloc allowed) --------
__device__ int   g_deg[NN];
__device__ int   g_cur[NN];
__device__ int   g_rowptr[NN + 2];
__device__ int   g_part[SCAN_BLOCKS];
__device__ int2  g_edge[EE];              // {src, float_bits(val)} sorted by dst

__device__ __half g_Hh[(size_t)NN * HH];  // relu(spmm(X)@Wb), fp16 [N,128]
__device__ float g_Hm[(size_t)NN * HH];   // spmm(H)                [N,128]
__device__ float g_mz[(size_t)NN * HH];   // Hm @ Wm2 = masked_z
__device__ float g_M2[CC * CC];           // A^T (I - A^T)^{-1}
__device__ float g_Wm2[HH * HH];          // folded W_mean
__device__ float g_lut[CC * LUT_PTS];     // pred_label LUT per concept

// =====================================================================
// K0a: M2 = A^T @ inv(I - A^T).  One 32x32 block.
// =====================================================================
__global__ void k_prep(const float* __restrict__ A)
{
    __shared__ float B[32][33];
    __shared__ float Inv[32][33];
    int cc = threadIdx.x;
    int r  = threadIdx.y;
    B[r][cc]   = (r == cc ? 1.f : 0.f) - A[cc * 32 + r];
    Inv[r][cc] = (r == cc ? 1.f : 0.f);
    __syncthreads();

    for (int k = 0; k < 32; k++) {
        float piv = B[k][k];
        __syncthreads();
        if (r == k) {
            float inv = 1.f / piv;
            B[k][cc]   *= inv;
            Inv[k][cc] *= inv;
        }
        __syncthreads();
        float f  = B[r][k];
        float bk = B[k][cc];
        float ik = Inv[k][cc];
        __syncthreads();
        if (r != k) {
            B[r][cc]   -= f * bk;
            Inv[r][cc] -= f * ik;
        }
        __syncthreads();
    }
    float acc = 0.f;
    #pragma unroll
    for (int j = 0; j < 32; j++)
        acc += A[j * 32 + r] * Inv[j][cc];
    g_M2[r * 32 + cc] = acc;
}

// =====================================================================
// K0b: fold M2 into W_mean; ALSO zero g_deg (grid-stride) to save a launch.
// =====================================================================
__global__ void k_fold(const float* __restrict__ Wm)
{
    int idx = blockIdx.x * blockDim.x + threadIdx.x;
    int h  = idx >> 7;
    int cd = idx & 127;
    int c  = cd >> 2;
    int d  = cd & 3;
    float acc = 0.f;
    #pragma unroll
    for (int k = 0; k < 32; k++)
        acc += g_M2[c * 32 + k] * Wm[h * 128 + k * 4 + d];
    g_Wm2[h * 128 + cd] = acc;
    // zero degree histogram (16384 threads cover NN)
    for (int i = idx; i < NN; i += 64 * 256) g_deg[i] = 0;
}

// =====================================================================
// K0c: build pred_label LUT.
// T[c][i] = bl2[c] + sum_g Wl2[c,g] * elu(x_i*Wl1[c,g] + bl1[c,g])
// x_i = -8 + i/128.   grid = 32 (c), block = 256.
// =====================================================================
__global__ void k_lut(const float* __restrict__ Wl1, const float* __restrict__ bl1,
                      const float* __restrict__ Wl2, const float* __restrict__ bl2)
{
    __shared__ float w1[32], b1[32], w2[32];
    int c = blockIdx.x;
    int tid = threadIdx.x;
    if (tid < 32) {
        w1[tid] = Wl1[c * 32 + tid];
        b1[tid] = bl1[c * 32 + tid];
        w2[tid] = Wl2[c * 32 + tid];
    }
    __syncthreads();
    float b2 = bl2[c];
    for (int i = tid; i < LUT_PTS; i += 256) {
        float x = -8.f + (float)i * (1.f / 128.f);
        float s = b2;
        #pragma unroll
        for (int g = 0; g < 32; g++) {
            float t = fmaf(x, w1[g], b1[g]);
            float h = t > 0.f ? t : (__expf(t) - 1.f);
            s = fmaf(h, w2[g], s);
        }
        g_lut[c * LUT_PTS + i] = s;
    }
}

// =====================================================================
// Counting sort of edges by dst
// =====================================================================
__global__ void k_hist(const int* __restrict__ dst)
{
    int i = blockIdx.x * blockDim.x + threadIdx.x;
    int stride = gridDim.x * blockDim.x;
    for (int e = i; e < EE; e += stride)
        atomicAdd(&g_deg[__ldg(dst + e)], 1);
}

__global__ void k_scan1()
{
    __shared__ int wsum[16];
    int tid  = threadIdx.x;
    int base = blockIdx.x * SCAN_ELEMS;
    int i0   = base + 2 * tid;
    int a = (i0     < NN) ? g_deg[i0]     : 0;
    int b = (i0 + 1 < NN) ? g_deg[i0 + 1] : 0;
    int s = a + b;
    int lane = tid & 31, w = tid >> 5;
    int incl = s;
    #pragma unroll
    for (int d = 1; d < 32; d <<= 1) {
        int t = __shfl_up_sync(0xffffffff, incl, d);
        if (lane >= d) incl += t;
    }
    if (lane == 31) wsum[w] = incl;
    __syncthreads();
    if (tid < 16) {
        int v = wsum[tid];
        int iv = v;
        #pragma unroll
        for (int d = 1; d < 16; d <<= 1) {
            int t = __shfl_up_sync(0xffff, iv, d);
            if (tid >= d) iv += t;
        }
        wsum[tid] = iv - v;
    }
    __syncthreads();
    int excl = wsum[w] + incl - s;
    if (i0 <= NN)     g_rowptr[i0]     = excl;
    if (i0 + 1 <= NN) g_rowptr[i0 + 1] = excl + a;
    if (tid == SCAN_TPB - 1) g_part[blockIdx.x] = excl + s;
}

__global__ void k_scan2()
{
    if (threadIdx.x == 0) {
        int run = 0;
        for (int i = 0; i < SCAN_BLOCKS; i++) {
            int v = g_part[i];
            g_part[i] = run;
            run += v;
        }
    }
}

__global__ void k_scan3()
{
    int i = blockIdx.x * blockDim.x + threadIdx.x;
    if (i <= NN) {
        int r = g_rowptr[i] + g_part[i >> 10];
        g_rowptr[i] = r;
        if (i < NN) g_cur[i] = r;
    }
}

__global__ void k_scatter(const int* __restrict__ src,
                          const int* __restrict__ dst,
                          const float* __restrict__ val)
{
    int i = blockIdx.x * blockDim.x + threadIdx.x;
    int stride = gridDim.x * blockDim.x;
    for (int e = i; e < EE; e += stride) {
        int d = __ldg(dst + e);
        int pos = atomicAdd(&g_cur[d], 1);
        g_edge[pos] = make_int2(__ldg(src + e), __float_as_int(__ldg(val + e)));
    }
}

// =====================================================================
// k_enc: fused  T = spmm(X) ;  H = relu(T @ W_base), stored fp16
// warp per node (grid-stride). 8-deep load batches for MLP.
// =====================================================================
__global__ void __launch_bounds__(256) k_enc(const float* __restrict__ X,
                                             const float* __restrict__ Wb)
{
    __shared__ float Ws[32 * 128];   // W_base, row-major [k][j]
    __shared__ float Ts[8][34];      // per-warp T broadcast buffer
    int tid = threadIdx.x;
    for (int i = tid; i < 32 * 128; i += 256) Ws[i] = Wb[i];
    __syncthreads();

    const int lane = tid & 31;
    const int warp = tid >> 5;
    unsigned gw = blockIdx.x * 8 + warp;
    unsigned nw = gridDim.x * 8;
    const float4* Ws4 = reinterpret_cast<const float4*>(Ws);

    for (unsigned n = gw; n < NN; n += nw) {
        int s0 = g_rowptr[n], s1 = g_rowptr[n + 1];
        float acc = 0.f;
        int e = s0;
        for (; e + 8 <= s1; e += 8) {
            int2 p[8];
            #pragma unroll
            for (int j = 0; j < 8; j++) p[j] = g_edge[e + j];
            float x[8];
            #pragma unroll
            for (int j = 0; j < 8; j++)
                x[j] = __ldg(X + (size_t)p[j].x * 32 + lane);
            #pragma unroll
            for (int j = 0; j < 8; j++)
                acc = fmaf(__int_as_float(p[j].y), x[j], acc);
        }
        for (; e + 4 <= s1; e += 4) {
            int2 p[4];
            #pragma unroll
            for (int j = 0; j < 4; j++) p[j] = g_edge[e + j];
            float x[4];
            #pragma unroll
            for (int j = 0; j < 4; j++)
                x[j] = __ldg(X + (size_t)p[j].x * 32 + lane);
            #pragma unroll
            for (int j = 0; j < 4; j++)
                acc = fmaf(__int_as_float(p[j].y), x[j], acc);
        }
        for (; e < s1; e++) {
            int2 p = g_edge[e];
            acc = fmaf(__int_as_float(p.y), __ldg(X + (size_t)p.x * 32 + lane), acc);
        }
        Ts[warp][lane] = acc;
        __syncwarp();

        float4 h = make_float4(0.f, 0.f, 0.f, 0.f);
        #pragma unroll
        for (int k = 0; k < 32; k++) {
            float tk = Ts[warp][k];
            float4 wv = Ws4[k * 32 + lane];
            h.x = fmaf(tk, wv.x, h.x); h.y = fmaf(tk, wv.y, h.y);
            h.z = fmaf(tk, wv.z, h.z); h.w = fmaf(tk, wv.w, h.w);
        }
        h.x = h.x > 0.f ? h.x : 0.f; h.y = h.y > 0.f ? h.y : 0.f;
        h.z = h.z > 0.f ? h.z : 0.f; h.w = h.w > 0.f ? h.w : 0.f;
        __half2 a = __floats2half2_rn(h.x, h.y);
        __half2 b = __floats2half2_rn(h.z, h.w);
        uint2 pk;
        pk.x = *reinterpret_cast<unsigned*>(&a);
        pk.y = *reinterpret_cast<unsigned*>(&b);
        reinterpret_cast<uint2*>(g_Hh)[(size_t)n * 32 + lane] = pk;
        __syncwarp();
    }
}

// =====================================================================
// spmm wide: Hm[n,:128] = sum_{e in row n} val[e] * H[src[e], :128]
// warp per node, lane handles 4 columns (fp16x4 = 8B load per edge).
// 8-deep front-batched load groups for MLP. fp32 accumulation.
// =====================================================================
__global__ void __launch_bounds__(256) k_spmm_wide()
{
    int lane = threadIdx.x & 31;
    int n = (blockIdx.x * blockDim.x + threadIdx.x) >> 5;
    if (n >= NN) return;
    int s0 = g_rowptr[n], s1 = g_rowptr[n + 1];
    const uint2* Hp = reinterpret_cast<const uint2*>(g_Hh);
    float4 acc = make_float4(0.f, 0.f, 0.f, 0.f);
    int e = s0;
    for (; e + 8 <= s1; e += 8) {
        int2 p[8];
        #pragma unroll
        for (int j = 0; j < 8; j++) p[j] = g_edge[e + j];
        uint2 r[8];
        #pragma unroll
        for (int j = 0; j < 8; j++)
            r[j] = __ldg(Hp + (size_t)p[j].x * 32 + lane);
        #pragma unroll
        for (int j = 0; j < 8; j++) {
            float v = __int_as_float(p[j].y);
            float2 a0 = __half22float2(*reinterpret_cast<__half2*>(&r[j].x));
            float2 b0 = __half22float2(*reinterpret_cast<__half2*>(&r[j].y));
            acc.x = fmaf(v, a0.x, acc.x); acc.y = fmaf(v, a0.y, acc.y);
            acc.z = fmaf(v, b0.x, acc.z); acc.w = fmaf(v, b0.y, acc.w);
        }
    }
    for (; e + 4 <= s1; e += 4) {
        int2 p[4];
        #pragma unroll
        for (int j = 0; j < 4; j++) p[j] = g_edge[e + j];
        uint2 r[4];
        #pragma unroll
        for (int j = 0; j < 4; j++)
            r[j] = __ldg(Hp + (size_t)p[j].x * 32 + lane);
        #pragma unroll
        for (int j = 0; j < 4; j++) {
            float v = __int_as_float(p[j].y);
            float2 a0 = __half22float2(*reinterpret_cast<__half2*>(&r[j].x));
            float2 b0 = __half22float2(*reinterpret_cast<__half2*>(&r[j].y));
            acc.x = fmaf(v, a0.x, acc.x); acc.y = fmaf(v, a0.y, acc.y);
            acc.z = fmaf(v, b0.x, acc.z); acc.w = fmaf(v, b0.y, acc.w);
        }
    }
    for (; e < s1; e++) {
        int2 p = g_edge[e];
        float v = __int_as_float(p.y);
        uint2 r0 = __ldg(Hp + (size_t)p.x * 32 + lane);
        float2 a0 = __half22float2(*reinterpret_cast<__half2*>(&r0.x));
        float2 b0 = __half22float2(*reinterpret_cast<__half2*>(&r0.y));
        acc.x = fmaf(v, a0.x, acc.x); acc.y = fmaf(v, a0.y, acc.y);
        acc.z = fmaf(v, b0.x, acc.z); acc.w = fmaf(v, b0.y, acc.w);
    }
    reinterpret_cast<float4*>(g_Hm)[(size_t)n * 32 + lane] = acc;
}

// =====================================================================
// K3: mz = Hm @ Wm2   [N,128]@[128,128]  (proven R6 tiling)
// =====================================================================
#define HS_STRIDE 132
#define MM_SMEM   ((64 * HS_STRIDE + 32 * 128) * 4)   // 50176 bytes

__global__ void __launch_bounds__(256) k_mm()
{
    extern __shared__ float dsm[];
    float* Hs = dsm;                     // [64][132]
    float* Wt = dsm + 64 * HS_STRIDE;    // [32][128]
    int tid  = threadIdx.x;
    int base = blockIdx.x * 64;

    for (int i = tid; i < 64 * 128; i += 256) {
        int r = i >> 7, k = i & 127;
        int row = base + r;
        Hs[r * HS_STRIDE + k] = (row < NN) ? g_Hm[(size_t)row * 128 + k] : 0.f;
    }

    const int tx = tid & 15;
    const int ty = tid >> 4;
    const int j0 = tx * 4;
    const int r0 = ty * 4;
    float acc[4][8];
    #pragma unroll
    for (int r = 0; r < 4; r++)
        #pragma unroll
        for (int c = 0; c < 8; c++) acc[r][c] = 0.f;

    for (int k0 = 0; k0 < 128; k0 += 32) {
        __syncthreads();
        for (int i = tid; i < 32 * 128; i += 256)
            Wt[i] = g_Wm2[(size_t)(k0 + (i >> 7)) * 128 + (i & 127)];
        __syncthreads();
        #pragma unroll
        for (int kk = 0; kk < 32; kk++) {
            float4 wa = *reinterpret_cast<const float4*>(&Wt[kk * 128 + j0]);
            float4 wb = *reinterpret_cast<const float4*>(&Wt[kk * 128 + 64 + j0]);
            #pragma unroll
            for (int r = 0; r < 4; r++) {
                float h = Hs[(r0 + r) * HS_STRIDE + k0 + kk];
                acc[r][0] = fmaf(h, wa.x, acc[r][0]);
                acc[r][1] = fmaf(h, wa.y, acc[r][1]);
                acc[r][2] = fmaf(h, wa.z, acc[r][2]);
                acc[r][3] = fmaf(h, wa.w, acc[r][3]);
                acc[r][4] = fmaf(h, wb.x, acc[r][4]);
                acc[r][5] = fmaf(h, wb.y, acc[r][5]);
                acc[r][6] = fmaf(h, wb.z, acc[r][6]);
                acc[r][7] = fmaf(h, wb.w, acc[r][7]);
            }
        }
    }
    #pragma unroll
    for (int r = 0; r < 4; r++) {
        int row = base + r0 + r;
        if (row < NN) {
            float4 oa = make_float4(acc[r][0], acc[r][1], acc[r][2], acc[r][3]);
            float4 ob = make_float4(acc[r][4], acc[r][5], acc[r][6], acc[r][7]);
            *reinterpret_cast<float4*>(&g_mz[(size_t)row * 128 + j0])      = oa;
            *reinterpret_cast<float4*>(&g_mz[(size_t)row * 128 + 64 + j0]) = ob;
        }
    }
}

// =====================================================================
// K5: fused epilogue. Warp per node-PAIR, lane per concept.
// pred_label via per-concept LUT (removes half the MUFU work).
// =====================================================================
#define OFF_W1   0
#define OFF_W2   4224
#define OFF_BZ1  8448                     // bz1[c*132+g] scalar table
#define OFF_AT   12672
#define OFF_WREC 16896
#define OFF_BZ2  21120
#define OFF_BREC 21280
#define OFF_ZBUF 21312                    // 8 warps * 2 nodes * 132
#define OFF_LAB  (21312 + 8 * 264)        // 8 warps * 2 nodes * 32
#define SMEM_FLOATS (OFF_LAB + 8 * 64)    // 23936 floats = 95744 bytes

__global__ void __launch_bounds__(256) k_epi(
    const float* __restrict__ label, const float* __restrict__ noise,
    const float* __restrict__ A,
    const float* __restrict__ Wz1, const float* __restrict__ bz1,
    const float* __restrict__ Wz2, const float* __restrict__ bz2,
    const float* __restrict__ Wrec, const float* __restrict__ brec,
    float* __restrict__ out_rec, float* __restrict__ out_pred)
{
    extern __shared__ float sm[];
    int tid = threadIdx.x;

    for (int i = tid; i < 4096; i += 256) {
        int c = i >> 7, r = i & 127, g = r >> 2, d = r & 3;
        sm[OFF_W1 + c * 132 + g * 4 + d] = Wz1[c * 128 + d * 32 + g];
        sm[OFF_W2 + c * 132 + g * 4 + d] = Wz2[c * 128 + g * 4 + d];
        int k = i >> 5, j = i & 31;
        sm[OFF_WREC + j * 132 + k] = Wrec[k * 32 + j];
    }
    for (int i = tid; i < 1024; i += 256) {
        int k = i >> 5, c = i & 31;
        sm[OFF_AT + c * 132 + k] = A[k * 32 + c];
        int cc = i >> 5, g = i & 31;
        sm[OFF_BZ1 + cc * 132 + g] = bz1[cc * 32 + g];
    }
    for (int i = tid; i < 128; i += 256) sm[OFF_BZ2 + i] = bz2[i];
    if (tid < 32) sm[OFF_BREC + tid] = brec[tid];
    __syncthreads();

    const int warp = tid >> 5;
    const int lane = tid & 31;
    unsigned gw = blockIdx.x * 8 + warp;
    unsigned nwrp = gridDim.x * 8;

    float* zbA = sm + OFF_ZBUF + warp * 264;
    float* zbB = zbA + 132;
    float* lbA = sm + OFF_LAB + warp * 64;
    float* lbB = lbA + 32;
    const float* w1p = sm + OFF_W1   + lane * 132;
    const float* w2p = sm + OFF_W2   + lane * 132;
    const float* bzp = sm + OFF_BZ1  + lane * 132;
    const float* atp = sm + OFF_AT   + lane * 132;
    const float* wrp = sm + OFF_WREC + lane * 132;
    const float* lut = g_lut + lane * LUT_PTS;
    const float  SQL = 0.0316227766016838f;   // sqrt(1e-3)

    // NN is even: pair (n, n+1) always valid when n < NN
    for (unsigned n = gw * 2; n < NN; n += nwrp * 2) {
        unsigned nA = n, nB = n + 1;
        float4 mzA = *reinterpret_cast<const float4*>(g_mz + (size_t)nA * 128 + lane * 4);
        float4 mzB = *reinterpret_cast<const float4*>(g_mz + (size_t)nB * 128 + lane * 4);
        float4 nzA = __ldg(reinterpret_cast<const float4*>(noise + (size_t)nA * 128) + lane);
        float4 nzB = __ldg(reinterpret_cast<const float4*>(noise + (size_t)nB * 128) + lane);
        lbA[lane] = __ldg(label + (size_t)nA * 32 + lane);
        lbB[lane] = __ldg(label + (size_t)nB * 32 + lane);
        __syncwarp();

        float mlA = 0.f, mlB = 0.f;
        #pragma unroll
        for (int k = 0; k < 32; k += 4) {
            float4 a4 = *reinterpret_cast<const float4*>(atp + k);
            float4 lA = *reinterpret_cast<const float4*>(lbA + k);
            float4 lB = *reinterpret_cast<const float4*>(lbB + k);
            mlA = fmaf(lA.x, a4.x, mlA); mlA = fmaf(lA.y, a4.y, mlA);
            mlA = fmaf(lA.z, a4.z, mlA); mlA = fmaf(lA.w, a4.w, mlA);
            mlB = fmaf(lB.x, a4.x, mlB); mlB = fmaf(lB.y, a4.y, mlB);
            mlB = fmaf(lB.z, a4.z, mlB); mlB = fmaf(lB.w, a4.w, mlB);
        }

        // pred_label via LUT lerp: u = (ml+8)*128
        float uA = fminf(fmaxf(fmaf(mlA, 128.f, 1024.f), 0.f), 2047.99f);
        float uB = fminf(fmaxf(fmaf(mlB, 128.f, 1024.f), 0.f), 2047.99f);
        float fiA = floorf(uA), fiB = floorf(uB);
        int iA = (int)fiA, iB = (int)fiB;
        float t0A = __ldg(lut + iA), t1A = __ldg(lut + iA + 1);
        float t0B = __ldg(lut + iB), t1B = __ldg(lut + iB + 1);
        float predA = fmaf(t1A - t0A, uA - fiA, t0A);
        float predB = fmaf(t1B - t0B, uB - fiB, t0B);

        float4 z2A = *reinterpret_cast<const float4*>(sm + OFF_BZ2 + lane * 4);
        float4 z2B = z2A;

        #pragma unroll 4
        for (int g = 0; g < 32; g++) {
            float4 w1 = *reinterpret_cast<const float4*>(w1p + g * 4);
            float  bz = bzp[g];
            float4 w2 = *reinterpret_cast<const float4*>(w2p + g * 4);

            float tA = bz;
            tA = fmaf(mzA.x, w1.x, tA); tA = fmaf(mzA.y, w1.y, tA);
            tA = fmaf(mzA.z, w1.z, tA); tA = fmaf(mzA.w, w1.w, tA);
            float hzA = tA > 0.f ? tA : (__expf(tA) - 1.f);
            z2A.x = fmaf(hzA, w2.x, z2A.x); z2A.y = fmaf(hzA, w2.y, z2A.y);
            z2A.z = fmaf(hzA, w2.z, z2A.z); z2A.w = fmaf(hzA, w2.w, z2A.w);

            float tB = bz;
            tB = fmaf(mzB.x, w1.x, tB); tB = fmaf(mzB.y, w1.y, tB);
            tB = fmaf(mzB.z, w1.z, tB); tB = fmaf(mzB.w, w1.w, tB);
            float hzB = tB > 0.f ? tB : (__expf(tB) - 1.f);
            z2B.x = fmaf(hzB, w2.x, z2B.x); z2B.y = fmaf(hzB, w2.y, z2B.y);
            z2B.z = fmaf(hzB, w2.z, z2B.z); z2B.w = fmaf(hzB, w2.w, z2B.w);
        }

        float4 zA, zB;
        zA.x = fmaf(SQL, nzA.x, z2A.x); zA.y = fmaf(SQL, nzA.y, z2A.y);
        zA.z = fmaf(SQL, nzA.z, z2A.z); zA.w = fmaf(SQL, nzA.w, z2A.w);
        zB.x = fmaf(SQL, nzB.x, z2B.x); zB.y = fmaf(SQL, nzB.y, z2B.y);
        zB.z = fmaf(SQL, nzB.z, z2B.z); zB.w = fmaf(SQL, nzB.w, z2B.w);
        *reinterpret_cast<float4*>(zbA + lane * 4) = zA;
        *reinterpret_cast<float4*>(zbB + lane * 4) = zB;
        __syncwarp();

        float accA = sm[OFF_BREC + lane];
        float accB = accA;
        #pragma unroll
        for (int k = 0; k < 128; k += 4) {
            float4 wr = *reinterpret_cast<const float4*>(wrp + k);
            float4 vA = *reinterpret_cast<const float4*>(zbA + k);
            float4 vB = *reinterpret_cast<const float4*>(zbB + k);
            accA = fmaf(vA.x, wr.x, accA); accA = fmaf(vA.y, wr.y, accA);
            accA = fmaf(vA.z, wr.z, accA); accA = fmaf(vA.w, wr.w, accA);
            accB = fmaf(vB.x, wr.x, accB); accB = fmaf(vB.y, wr.y, accB);
            accB = fmaf(vB.z, wr.z, accB); accB = fmaf(vB.w, wr.w, accB);
        }
        out_rec[(size_t)nA * 32 + lane]  = accA;
        out_rec[(size_t)nB * 32 + lane]  = accB;
        out_pred[(size_t)nA * 32 + lane] = predA;
        out_pred[(size_t)nB * 32 + lane] = predB;
        __syncwarp();
    }
}

// =====================================================================
// launch
// =====================================================================
extern "C" void kernel_launch(void* const* d_in, const int* in_sizes, int n_in,
                              void* d_out, int out_size)
{
    const float* X      = (const float*)d_in[0];
    const float* label  = (const float*)d_in[1];
    const float* eval_  = (const float*)d_in[2];
    const float* noise  = (const float*)d_in[3];
    const float* Wb     = (const float*)d_in[4];
    const float* Wm     = (const float*)d_in[5];
    // d_in[6] = W_logstd -> result discarded in reference, skipped entirely
    const float* A      = (const float*)d_in[7];
    const float* Wz1    = (const float*)d_in[8];
    const float* bz1    = (const float*)d_in[9];
    const float* Wz2    = (const float*)d_in[10];
    const float* bz2    = (const float*)d_in[11];
    const float* Wl1    = (const float*)d_in[12];
    const float* bl1    = (const float*)d_in[13];
    const float* Wl2    = (const float*)d_in[14];
    const float* bl2    = (const float*)d_in[15];
    const float* Wrec   = (const float*)d_in[16];
    const float* brec   = (const float*)d_in[17];
    const int*   esrc   = (const int*)d_in[18];
    const int*   edst   = (const int*)d_in[19];

    float* out_rec  = (float*)d_out;
    float* out_pred = out_rec + (size_t)NN * 32;

    cudaFuncSetAttribute(k_epi, cudaFuncAttributeMaxDynamicSharedMemorySize,
                         SMEM_FLOATS * (int)sizeof(float));
    cudaFuncSetAttribute(k_mm, cudaFuncAttributeMaxDynamicSharedMemorySize,
                         MM_SMEM);

    // tiny weight prep (k_fold also zeroes g_deg) + pred_label LUT
    k_prep<<<1, dim3(32, 32)>>>(A);
    k_fold<<<64, 256>>>(Wm);
    k_lut<<<32, 256>>>(Wl1, bl1, Wl2, bl2);

    // counting sort of edges by dst -> CSR (paired {src, val})
    k_hist<<<2048, 256>>>(edst);
    k_scan1<<<SCAN_BLOCKS, SCAN_TPB>>>();
    k_scan2<<<1, 32>>>();
    k_scan3<<<(NN + 256) / 256, 256>>>();
    k_scatter<<<2048, 256>>>(esrc, edst, eval_);

    // main pipeline
    k_enc<<<1536, 256>>>(X, Wb);                        // H = relu(spmm(X) @ Wb), fp16
    k_spmm_wide<<<(NN * 32 + 255) / 256, 256>>>();      // Hm = spmm(H)  (fp32 accum)
    k_mm<<<(NN + 63) / 64, 256, MM_SMEM>>>();           // mz = Hm @ Wm2
    k_epi<<<296, 256, SMEM_FLOATS * sizeof(float)>>>(
        label, noise, A, Wz1, bz1, Wz2, bz2,
        Wrec, brec, out_rec, out_pred);
}